// round 5
// baseline (speedup 1.0000x reference)
#include <cuda_runtime.h>
#include <cstdint>

#define B_  16
#define NC_ 10
#define H_  6
#define C_  384
#define HD_ 64
#define T_  197
#define N_  196
#define BH_ (B_*H_)
#define CH_ (NC_*H_)
#define SCALE_ 0.125f

// weight segment offsets inside g_wr (floats)
#define OFF_WQK  0
#define OFF_WQK2 147456
#define OFF_WV   294912
#define OFF_WR   442368
#define OFF_W1   589824
#define OFF_W2   1179648
#define WR_TOT   1769472

__device__ float g_n1 [26*C_];
__device__ float g_n2x[B_*N_*C_];
__device__ float g_n2a[NC_*N_*C_];
__device__ float g_qv [NC_*2*C_];
__device__ float g_k  [B_*C_];
__device__ float g_attn[B_*CH_];
__device__ float g_ctx[B_*C_];
__device__ float g_heads[3*BH_*N_*HD_];   // qh, q2, vr
__device__ float g_aheads[2*CH_*N_*HD_];  // kh, k2
__device__ float g_tmp[BH_*N_*N_];
__device__ float g_rectH[B_*N_*C_];
__device__ float g_xx [B_*T_*C_];
__device__ float g_hdn[B_*T_*C_];
__device__ float g_h1 [B_*T_*4*C_];
__device__ float g_wr [WR_TOT];

__device__ __forceinline__ float to_tf32(float x) {
    uint32_t u;
    asm("cvt.rna.tf32.f32 %0, %1;" : "=r"(u) : "f"(x));
    return __uint_as_float(u);
}
#define U32(x) __float_as_uint(x)

__device__ __forceinline__ void mma8(float* c, uint32_t a0, uint32_t a1, uint32_t a2, uint32_t a3,
                                     uint32_t b0, uint32_t b1)
{
    asm volatile("mma.sync.aligned.m16n8k8.row.col.f32.tf32.tf32.f32 "
                 "{%0,%1,%2,%3},{%4,%5,%6,%7},{%8,%9},{%0,%1,%2,%3};\n"
                 : "+f"(c[0]), "+f"(c[1]), "+f"(c[2]), "+f"(c[3])
                 : "r"(a0), "r"(a1), "r"(a2), "r"(a3), "r"(b0), "r"(b1));
}

__device__ __forceinline__ void cp16(uint32_t dst, const void* src, bool p) {
    int sz = p ? 16 : 0;
    asm volatile("cp.async.cg.shared.global [%0], [%1], 16, %2;" :: "r"(dst), "l"(src), "r"(sz));
}

__device__ __forceinline__ float gelu_f(float x) {
    return 0.5f * x * (1.f + erff(x * 0.7071067811865475f));
}

// ---------------- weight pre-rounding (single launch) ----------------
__global__ void round6(const float* __restrict__ w0, const float* __restrict__ w1,
                       const float* __restrict__ w2, const float* __restrict__ w3,
                       const float* __restrict__ w4, const float* __restrict__ w5,
                       float* __restrict__ dst)
{
    int i = (blockIdx.x * 256 + threadIdx.x) * 4;
    if (i >= WR_TOT) return;
    const float* src; int off;
    if      (i < OFF_WQK2) { src = w0; off = OFF_WQK;  }
    else if (i < OFF_WV)   { src = w1; off = OFF_WQK2; }
    else if (i < OFF_WR)   { src = w2; off = OFF_WV;   }
    else if (i < OFF_W1)   { src = w3; off = OFF_WR;   }
    else if (i < OFF_W2)   { src = w4; off = OFF_W1;   }
    else                   { src = w5; off = OFF_W2;   }
    float4 v = *(const float4*)(src + i - off);
    float4 r = make_float4(to_tf32(v.x), to_tf32(v.y), to_tf32(v.z), to_tf32(v.w));
    *(float4*)(dst + i) = r;
}

// ---------------- LayerNorm (optional tf32 rounding of output) ----------------
__global__ void ln_kernel(const float* __restrict__ in, float* __restrict__ out,
                          const float* __restrict__ g, const float* __restrict__ bt,
                          int rows, int inner, long outer_stride, long inner_stride, int rnd)
{
    int row = blockIdx.x;
    if (row >= rows) return;
    const float* src = in + (long)(row / inner) * outer_stride + (long)(row % inner) * inner_stride;
    int t = threadIdx.x;
    float v[3]; float s = 0.f;
#pragma unroll
    for (int i = 0; i < 3; i++) { v[i] = src[t + i*128]; s += v[i]; }
    __shared__ float red[4];
#pragma unroll
    for (int o = 16; o > 0; o >>= 1) s += __shfl_xor_sync(0xffffffffu, s, o);
    if ((t & 31) == 0) red[t >> 5] = s;
    __syncthreads();
    float mean = (red[0] + red[1] + red[2] + red[3]) * (1.f/384.f);
    float q = 0.f;
#pragma unroll
    for (int i = 0; i < 3; i++) { float d = v[i] - mean; q += d*d; }
#pragma unroll
    for (int o = 16; o > 0; o >>= 1) q += __shfl_xor_sync(0xffffffffu, q, o);
    __syncthreads();
    if ((t & 31) == 0) red[t >> 5] = q;
    __syncthreads();
    float var = (red[0] + red[1] + red[2] + red[3]) * (1.f/384.f);
    float rs = rsqrtf(var + 1e-5f);
    float* dst = out + (long)row * C_;
#pragma unroll
    for (int i = 0; i < 3; i++) {
        int c = t + i*128;
        float o = (v[i] - mean) * rs * g[c] + bt[c];
        dst[c] = rnd ? to_tf32(o) : o;
    }
}

// ---------------- small-M row GEMM (cls path), K=384, 4-way ILP ----------------
__global__ __launch_bounds__(256)
void rowgemm(const float* __restrict__ A, const float* __restrict__ W,
             const float* __restrict__ bias, float* __restrict__ out,
             int N, long out_stride)
{
    __shared__ float a_s[384];
    __shared__ float part[128];
    int row = blockIdx.x, cb = blockIdx.y * 128;
    int t = threadIdx.x;
    for (int i = t; i < 384; i += 256) a_s[i] = A[(size_t)row*384 + i];
    __syncthreads();
    int half = t >> 7, c = t & 127;
    int base = half * 192;
    float s0 = 0.f, s1 = 0.f, s2 = 0.f, s3 = 0.f;
    const float* Wp = W + (size_t)base*N + cb + c;
#pragma unroll 8
    for (int k = 0; k < 192; k += 4) {
        s0 += a_s[base+k]   * Wp[(size_t)(k)*N];
        s1 += a_s[base+k+1] * Wp[(size_t)(k+1)*N];
        s2 += a_s[base+k+2] * Wp[(size_t)(k+2)*N];
        s3 += a_s[base+k+3] * Wp[(size_t)(k+3)*N];
    }
    float s = (s0 + s1) + (s2 + s3);
    if (half) part[c] = s;
    __syncthreads();
    if (!half) {
        float v = s + part[c];
        if (bias) v += bias[cb + c];
        out[(size_t)row*out_stride + cb + c] = v;
    }
}

// ---------------- cls attention ----------------
__global__ void attn_cls_kernel(const float* __restrict__ qv, const float* __restrict__ k,
                                float* __restrict__ attn, float* __restrict__ ctx)
{
    int b = blockIdx.x, t = threadIdx.x;
    __shared__ float sl[CH_];
    if (t < CH_) {
        int n = t / H_, h = t % H_;
        float s = 0.f;
        for (int d = 0; d < HD_; d++) s += qv[n*2*C_ + h*HD_ + d] * k[b*C_ + h*HD_ + d];
        sl[t] = s * SCALE_;
    }
    __syncthreads();
    if (t < H_) {
        float mx = -1e30f;
        for (int n = 0; n < NC_; n++) mx = fmaxf(mx, sl[n*H_ + t]);
        float sum = 0.f;
        for (int n = 0; n < NC_; n++) { float e = expf(sl[n*H_ + t] - mx); sl[n*H_ + t] = e; sum += e; }
        float inv = 1.f / sum;
        for (int n = 0; n < NC_; n++) { sl[n*H_ + t] *= inv; attn[b*CH_ + n*H_ + t] = sl[n*H_ + t]; }
    }
    __syncthreads();
    {
        int h = t >> 6, d = t & 63;
        float s = 0.f;
        for (int n = 0; n < NC_; n++) s += sl[n*H_ + h] * qv[n*2*C_ + C_ + h*HD_ + d];
        ctx[b*C_ + t] = s;
    }
}

// 0: row-major; 1: head-major; 2: xx rows 1..196
__device__ __forceinline__ size_t out_map(int mode, int mm, int nn, int N)
{
    if (mode == 0) return (size_t)mm * N + nn;
    if (mode == 1) {
        int bq = mm / N_, n = mm % N_;
        return ((size_t)(bq*H_ + (nn >> 6)) * N_ + n) * HD_ + (nn & 63);
    }
    int bq = mm / N_, n = mm % N_;
    return ((size_t)bq*T_ + 1 + n) * C_ + nn;
}

// ---------------- 3-stage cp.async pipelined tf32 GEMM (128x64 tile) ----------
// A, W must be pre-rounded to tf32. grid.z batching via zA/zB/zO strides.
#define PAD_A 20
#define PAD_B 72
__global__ __launch_bounds__(256)
void gemm_pipe(const float* __restrict__ A, const float* __restrict__ W,
               const float* __restrict__ bias, const float* __restrict__ res,
               float* __restrict__ out, int M, int N, int K, int act, int mode, int rnd,
               long zA, long zB, long zO)
{
    __shared__ float As[3][128*PAD_A];
    __shared__ float Bs[3][16*PAD_B];
    A   += (size_t)blockIdx.z * zA;
    W   += (size_t)blockIdx.z * zB;
    out += (size_t)blockIdx.z * zO;

    int tid = threadIdx.x;
    int lane = tid & 31, warp = tid >> 5;
    int gid = lane >> 2, tig = lane & 3;
    int wm = warp >> 1, wn = warp & 1;
    int m0 = blockIdx.y * 128, n0 = blockIdx.x * 64;

    // staging tasks
    int ar0 = tid >> 1, ac0 = (tid & 1) * 2;     // A: 2 chunks per thread
    int brow = tid >> 4, bc4 = (tid & 15) * 4;   // B: 1 chunk per thread

    int nk = (K + 15) / 16;

    uint32_t aBase[3], bBase[3];
#pragma unroll
    for (int s = 0; s < 3; s++) {
        aBase[s] = (uint32_t)__cvta_generic_to_shared(&As[s][0]);
        bBase[s] = (uint32_t)__cvta_generic_to_shared(&Bs[s][0]);
    }

#define ISSUE(it_, st_) do { \
    int kk = (it_) * 16; \
    /* A: rows ar0, chunks ac0, ac0+1 */ \
    _Pragma("unroll") \
    for (int j = 0; j < 2; j++) { \
        int c4 = ac0 + j; \
        bool ok = (m0 + ar0 < M) && (kk + c4*4 + 4 <= K); \
        const float* src = A + (size_t)(m0 + ar0) * K + kk + c4*4; \
        cp16(aBase[st_] + (ar0*PAD_A + c4*4)*4, ok ? src : A, ok); \
    } \
    { \
        bool ok = (kk + brow < K); \
        const float* src = W + (size_t)(kk + brow) * N + n0 + bc4; \
        cp16(bBase[st_] + (brow*PAD_B + bc4)*4, ok ? src : W, ok); \
    } \
    asm volatile("cp.async.commit_group;" ::: "memory"); \
} while (0)

    ISSUE(0, 0);
    ISSUE(1, 1);

    float acc[2][4][4];
#pragma unroll
    for (int t = 0; t < 2; t++)
#pragma unroll
        for (int u = 0; u < 4; u++)
#pragma unroll
            for (int e = 0; e < 4; e++) acc[t][u][e] = 0.f;

    for (int it = 0; it < nk; it++) {
        asm volatile("cp.async.wait_group 1;" ::: "memory");
        __syncthreads();
        int st = it % 3;
        const float* Af = As[st];
        const float* Bf = Bs[st];
#pragma unroll
        for (int ks = 0; ks < 2; ks++) {
            int k = ks * 8;
            uint32_t a[2][4];
#pragma unroll
            for (int t = 0; t < 2; t++) {
                int mb = wm*32 + t*16;
                a[t][0] = U32(Af[(mb+gid)*PAD_A + k+tig]);
                a[t][1] = U32(Af[(mb+gid+8)*PAD_A + k+tig]);
                a[t][2] = U32(Af[(mb+gid)*PAD_A + k+tig+4]);
                a[t][3] = U32(Af[(mb+gid+8)*PAD_A + k+tig+4]);
            }
#pragma unroll
            for (int u = 0; u < 4; u++) {
                int cb = wn*32 + u*8;
                uint32_t b0 = U32(Bf[(k+tig)*PAD_B + cb+gid]);
                uint32_t b1 = U32(Bf[(k+tig+4)*PAD_B + cb+gid]);
                mma8(acc[0][u], a[0][0],a[0][1],a[0][2],a[0][3], b0,b1);
                mma8(acc[1][u], a[1][0],a[1][1],a[1][2],a[1][3], b0,b1);
            }
        }
        if (it + 2 < nk) {
            int st2 = (it + 2) % 3;
            ISSUE(it + 2, st2);
        }
    }
#undef ISSUE

#pragma unroll
    for (int t = 0; t < 2; t++) {
#pragma unroll
        for (int u = 0; u < 4; u++) {
            int rb = m0 + wm*32 + t*16 + gid;
            int cb = n0 + wn*32 + u*8 + 2*tig;
#pragma unroll
            for (int e = 0; e < 4; e++) {
                int r = rb + (e >> 1) * 8;
                int c = cb + (e & 1);
                if (r < M && c < N) {
                    float v = acc[t][u][e];
                    if (bias) v += bias[c];
                    if (act) v = gelu_f(v);
                    if (rnd) v = to_tf32(v);
                    size_t idx = out_map(mode, r, c, N);
                    if (res) v += res[idx];
                    out[idx] = v;
                }
            }
        }
    }
}

// ---------------- fused rectified attention core ----------------
__global__ __launch_bounds__(256, 1)
void fused_attn2(const float* __restrict__ qh, const float* __restrict__ kh,
                 const float* __restrict__ q2, const float* __restrict__ k2,
                 const float* __restrict__ w2all, float* __restrict__ tmp_out)
{
    __shared__ float sm_[8704];
    float* const kbuf0 = sm_;
    float* const kbuf1 = sm_ + 1088;
    float* const vbuf0 = sm_ + 2176;
    float* const vbuf1 = sm_ + 3264;
    float* const L_s   = sm_ + 4352;
    float* const R_s   = sm_ + 6528;

    int tid = threadIdx.x;
    int lane = tid & 31, warp = tid >> 5;
    int gid = lane >> 2, tig = lane & 3;
    int wm = warp >> 1, wn = warp & 1;

    int bh = blockIdx.z;
    int b = bh / H_, h = bh % H_;
    int n0 = blockIdx.y * 68;
    int p0 = blockIdx.x * 68;

    const float* qh_b = qh + (size_t)bh * N_ * HD_;
    const float* q2_b = q2 + (size_t)bh * N_ * HD_;

    uint32_t aq[8][4];
    for (int i = tid; i < 2048; i += 256) {
        int r = i >> 4, c4 = (i & 15) * 4;
        *(float4*)(sm_ + r*68 + c4) = *(const float4*)(qh_b + (size_t)(n0+r)*HD_ + c4);
    }
    __syncthreads();
    {
        int rb = warp * 16;
#pragma unroll
        for (int j = 0; j < 8; j++) {
            aq[j][0] = U32(sm_[(rb+gid)*68 + 8*j+tig]);
            aq[j][1] = U32(sm_[(rb+gid+8)*68 + 8*j+tig]);
            aq[j][2] = U32(sm_[(rb+gid)*68 + 8*j+tig+4]);
            aq[j][3] = U32(sm_[(rb+gid+8)*68 + 8*j+tig+4]);
        }
    }
    __syncthreads();
    uint32_t bq[8][2][2];
    for (int i = tid; i < 2048; i += 256) {
        int r = i >> 4, c4 = (i & 15) * 4;
        *(float4*)(sm_ + r*68 + c4) = *(const float4*)(q2_b + (size_t)(p0+r)*HD_ + c4);
    }
    __syncthreads();
    {
        int pb = warp * 16;
#pragma unroll
        for (int j = 0; j < 8; j++)
#pragma unroll
            for (int t = 0; t < 2; t++) {
                bq[j][t][0] = U32(sm_[(pb+8*t+gid)*68 + 8*j+tig]);
                bq[j][t][1] = U32(sm_[(pb+8*t+gid)*68 + 8*j+tig+4]);
            }
    }
    __syncthreads();

    float acc[2][8][4];
#pragma unroll
    for (int t = 0; t < 2; t++)
#pragma unroll
        for (int u = 0; u < 8; u++)
#pragma unroll
            for (int e = 0; e < 4; e++) acc[t][u][e] = 0.f;

    uint32_t kd0 = (uint32_t)__cvta_generic_to_shared(kbuf0);
    uint32_t kd1 = (uint32_t)__cvta_generic_to_shared(kbuf1);
    uint32_t vd0 = (uint32_t)__cvta_generic_to_shared(vbuf0);
    uint32_t vd1 = (uint32_t)__cvta_generic_to_shared(vbuf1);
    int prow = tid >> 4, pc4 = (tid & 15) * 4;

    {
        const float* kh_c = kh + (size_t)h * N_ * HD_;
        const float* k2_c = k2 + (size_t)h * N_ * HD_;
        cp16(kd0 + (prow*68 + pc4)*4, kh_c + (size_t)prow*HD_ + pc4, true);
        cp16(vd0 + (prow*68 + pc4)*4, k2_c + (size_t)prow*HD_ + pc4, true);
    }
    asm volatile("cp.async.commit_group;" ::: "memory");

    int buf = 0;
    for (int c = 0; c < NC_; c++) {
        float w2c = w2all[b*CH_ + h*NC_ + c];
        for (int mc = 0; mc < 13; mc++) {
            {
                int nc2 = c, nm = mc + 1;
                if (nm == 13) { nm = 0; nc2 = c + 1; }
                if (nc2 < NC_) {
                    const float* kh_c = kh + (size_t)(nc2*H_ + h) * N_ * HD_;
                    const float* k2_c = k2 + (size_t)(nc2*H_ + h) * N_ * HD_;
                    int m = nm*16 + prow;
                    bool ok = m < N_;
                    size_t off = ok ? ((size_t)m*HD_ + pc4) : 0;
                    uint32_t kd = buf ? kd0 : kd1;
                    uint32_t vd = buf ? vd0 : vd1;
                    cp16(kd + (prow*68 + pc4)*4, kh_c + off, ok);
                    cp16(vd + (prow*68 + pc4)*4, k2_c + off, ok);
                }
            }
            asm volatile("cp.async.commit_group;" ::: "memory");
            asm volatile("cp.async.wait_group 1;" ::: "memory");
            __syncthreads();

            const float* KT  = buf ? kbuf1 : kbuf0;
            const float* K2T = buf ? vbuf1 : vbuf0;

            float lacc[2][4];
#pragma unroll
            for (int t = 0; t < 2; t++)
#pragma unroll
                for (int e = 0; e < 4; e++) lacc[t][e] = 0.f;
#pragma unroll
            for (int j = 0; j < 8; j++) {
#pragma unroll
                for (int t = 0; t < 2; t++) {
                    uint32_t b0 = U32(KT[(8*t+gid)*68 + 8*j+tig]);
                    uint32_t b1 = U32(KT[(8*t+gid)*68 + 8*j+tig+4]);
                    mma8(lacc[t], aq[j][0],aq[j][1],aq[j][2],aq[j][3], b0,b1);
                }
            }
            float racc[2][4];
#pragma unroll
            for (int t = 0; t < 2; t++)
#pragma unroll
                for (int e = 0; e < 4; e++) racc[t][e] = 0.f;
#pragma unroll
            for (int j = 0; j < 8; j++) {
                uint32_t a0 = U32(K2T[gid*68 + 8*j+tig]);
                uint32_t a1 = U32(K2T[(gid+8)*68 + 8*j+tig]);
                uint32_t a2 = U32(K2T[gid*68 + 8*j+tig+4]);
                uint32_t a3 = U32(K2T[(gid+8)*68 + 8*j+tig+4]);
                mma8(racc[0], a0,a1,a2,a3, bq[j][0][0], bq[j][0][1]);
                mma8(racc[1], a0,a1,a2,a3, bq[j][1][0], bq[j][1][1]);
            }
            {
                int nr = warp*16 + gid;
#pragma unroll
                for (int t = 0; t < 2; t++) {
                    int mcol = 8*t + 2*tig;
                    L_s[mcol*136 + nr]       = to_tf32(w2c * fmaxf(0.f, -SCALE_*lacc[t][0]));
                    L_s[(mcol+1)*136 + nr]   = to_tf32(w2c * fmaxf(0.f, -SCALE_*lacc[t][1]));
                    L_s[mcol*136 + nr+8]     = to_tf32(w2c * fmaxf(0.f, -SCALE_*lacc[t][2]));
                    L_s[(mcol+1)*136 + nr+8] = to_tf32(w2c * fmaxf(0.f, -SCALE_*lacc[t][3]));
                    int pc = warp*16 + 8*t + 2*tig;
                    float2 lo = make_float2(to_tf32(fmaxf(0.f, SCALE_*racc[t][0])),
                                            to_tf32(fmaxf(0.f, SCALE_*racc[t][1])));
                    float2 hi = make_float2(to_tf32(fmaxf(0.f, SCALE_*racc[t][2])),
                                            to_tf32(fmaxf(0.f, SCALE_*racc[t][3])));
                    *(float2*)(R_s + gid*136 + pc)     = lo;
                    *(float2*)(R_s + (gid+8)*136 + pc) = hi;
                }
            }
            __syncthreads();
#pragma unroll
            for (int g = 0; g < 2; g++) {
                uint32_t a[2][4];
#pragma unroll
                for (int t = 0; t < 2; t++) {
                    int mb = wm*32 + t*16;
                    a[t][0] = U32(L_s[(8*g+tig)*136 + mb+gid]);
                    a[t][1] = U32(L_s[(8*g+tig)*136 + mb+gid+8]);
                    a[t][2] = U32(L_s[(8*g+tig+4)*136 + mb+gid]);
                    a[t][3] = U32(L_s[(8*g+tig+4)*136 + mb+gid+8]);
                }
#pragma unroll
                for (int u = 0; u < 8; u++) {
                    int cb = wn*64 + u*8;
                    uint32_t b0 = U32(R_s[(8*g+tig)*136 + cb+gid]);
                    uint32_t b1 = U32(R_s[(8*g+tig+4)*136 + cb+gid]);
                    mma8(acc[0][u], a[0][0],a[0][1],a[0][2],a[0][3], b0,b1);
                    mma8(acc[1][u], a[1][0],a[1][1],a[1][2],a[1][3], b0,b1);
                }
            }
            buf ^= 1;
        }
    }

    float* o = tmp_out + (size_t)bh * N_ * N_;
#pragma unroll
    for (int t = 0; t < 2; t++) {
#pragma unroll
        for (int u = 0; u < 8; u++) {
            int n = n0 + wm*32 + t*16 + gid;
            int p = p0 + wn*64 + u*8 + 2*tig;
            o[(size_t)n*N_ + p]         = to_tf32(acc[t][u][0]);
            o[(size_t)n*N_ + p + 1]     = to_tf32(acc[t][u][1]);
            o[(size_t)(n+8)*N_ + p]     = to_tf32(acc[t][u][2]);
            o[(size_t)(n+8)*N_ + p + 1] = to_tf32(acc[t][u][3]);
        }
    }
}

__global__ void copy_kernel(const float* __restrict__ src, float* __restrict__ dst, int n4)
{
    int i = blockIdx.x * blockDim.x + threadIdx.x;
    if (i < n4) ((float4*)dst)[i] = ((const float4*)src)[i];
}

extern "C" void kernel_launch(void* const* d_in, const int* in_sizes, int n_in,
                              void* d_out, int out_size)
{
    const float* x       = (const float*)d_in[0];
    const float* Wqv     = (const float*)d_in[1];
    const float* Wk      = (const float*)d_in[2];
    const float* Wq_proj = (const float*)d_in[3];
    const float* bq_proj = (const float*)d_in[4];
    const float* Wqk     = (const float*)d_in[5];
    const float* Wqk2    = (const float*)d_in[6];
    const float* Wv      = (const float*)d_in[7];
    const float* Wr_proj = (const float*)d_in[8];
    const float* br_proj = (const float*)d_in[9];
    const float* g1      = (const float*)d_in[10];
    const float* b1      = (const float*)d_in[11];
    const float* g2      = (const float*)d_in[12];
    const float* b2      = (const float*)d_in[13];
    const float* g3      = (const float*)d_in[14];
    const float* b3      = (const float*)d_in[15];
    const float* W1      = (const float*)d_in[16];
    const float* bm1     = (const float*)d_in[17];
    const float* W2      = (const float*)d_in[18];
    const float* bm2     = (const float*)d_in[19];
    float* outp = (float*)d_out;

    float *n1, *n2x, *n2a, *qv, *kb, *attn, *ctx, *heads, *aheads;
    float *tmp, *rectH, *xx, *hdn, *h1, *wr;
    cudaGetSymbolAddress((void**)&n1, g_n1);
    cudaGetSymbolAddress((void**)&n2x, g_n2x);
    cudaGetSymbolAddress((void**)&n2a, g_n2a);
    cudaGetSymbolAddress((void**)&qv, g_qv);
    cudaGetSymbolAddress((void**)&kb, g_k);
    cudaGetSymbolAddress((void**)&attn, g_attn);
    cudaGetSymbolAddress((void**)&ctx, g_ctx);
    cudaGetSymbolAddress((void**)&heads, g_heads);
    cudaGetSymbolAddress((void**)&aheads, g_aheads);
    cudaGetSymbolAddress((void**)&tmp, g_tmp);
    cudaGetSymbolAddress((void**)&rectH, g_rectH);
    cudaGetSymbolAddress((void**)&xx, g_xx);
    cudaGetSymbolAddress((void**)&hdn, g_hdn);
    cudaGetSymbolAddress((void**)&h1, g_h1);
    cudaGetSymbolAddress((void**)&wr, g_wr);

    const long zHx = (long)BH_*N_*HD_;   // x-side head buffer stride
    const long zHa = (long)CH_*N_*HD_;   // anchor-side
    float* qh  = heads;
    float* q2  = heads + zHx;
    float* vr  = heads + 2*zHx;
    float* kh  = aheads;
    float* k2  = aheads + zHa;

    // 0) pre-round all mma weights to tf32 (contiguous buffer)
    round6<<<(WR_TOT/4 + 255)/256, 256>>>(Wqk, Wqk2, Wv, Wr_proj, W1, W2, wr);

    // 1) LayerNorms (n2x/n2a rounded; n1 fp32 for the fp32 cls path)
    ln_kernel<<<26, 128>>>(x, n1, g1, b1, 26, 26, 0, (long)T_*C_, 0);
    ln_kernel<<<B_*N_, 128>>>(x + C_, n2x, g2, b2, B_*N_, N_, (long)T_*C_, C_, 1);
    ln_kernel<<<NC_*N_, 128>>>(x + (long)16*T_*C_ + C_, n2a, g2, b2, NC_*N_, N_, (long)T_*C_, C_, 1);

    // 2) cls path (fp32, row-parallel)
    rowgemm<<<dim3(NC_, 6), 256>>>(n1 + 16*C_, Wqv, nullptr, qv, 2*C_, 2*C_);
    rowgemm<<<dim3(B_, 3), 256>>>(n1, Wk, nullptr, kb, C_, C_);
    attn_cls_kernel<<<B_, 384>>>(qv, kb, attn, ctx);
    rowgemm<<<dim3(B_, 3), 256>>>(ctx, Wq_proj, bq_proj, xx, C_, (long)T_*C_);

    // 3) head projections: one launch per side (grid.z selects weight/output)
    gemm_pipe<<<dim3(6, 25, 3), 256>>>(n2x, wr + OFF_WQK, nullptr, nullptr, heads,
                                       B_*N_, C_, C_, 0, 1, 1, 0, 147456, zHx);
    gemm_pipe<<<dim3(6, 16, 2), 256>>>(n2a, wr + OFF_WQK, nullptr, nullptr, aheads,
                                       NC_*N_, C_, C_, 0, 1, 1, 0, 147456, zHa);

    // 4) fused rectified attention core
    dim3 gf(2, 2, BH_);
    fused_attn2<<<gf, 256>>>(qh, kh, q2, k2, attn, tmp);

    // 5) rect = tmp @ vr, batched over bh
    gemm_pipe<<<dim3(1, 2, BH_), 256>>>(tmp, vr, nullptr, nullptr, rectH,
                                        N_, HD_, N_, 0, 0, 1,
                                        (long)N_*N_, (long)N_*HD_, (long)N_*HD_);

    // 6) rect projection + residual -> xx rows 1..196
    gemm_pipe<<<dim3(6, 25, 1), 256>>>(rectH, wr + OFF_WR, br_proj, x, xx,
                                       B_*N_, C_, C_, 0, 2, 0, 0, 0, 0);

    // 7) MLP
    ln_kernel<<<B_*T_, 128>>>(xx, hdn, g3, b3, B_*T_, B_*T_, 0, C_, 1);
    gemm_pipe<<<dim3(24, 25, 1), 256>>>(hdn, wr + OFF_W1, bm1, nullptr, h1,
                                        B_*T_, 4*C_, C_, 1, 0, 1, 0, 0, 0);
    gemm_pipe<<<dim3(6, 25, 1), 256>>>(h1, wr + OFF_W2, bm2, xx, outp,
                                       B_*T_, C_, 4*C_, 0, 0, 0, 0, 0, 0);

    // 8) anchors pass-through
    int n4 = NC_*T_*C_/4;
    copy_kernel<<<(n4 + 255)/256, 256>>>(x + (long)16*T_*C_, outp + (long)16*T_*C_, n4);
}

// round 7
// speedup vs baseline: 1.3840x; 1.3840x over previous
#include <cuda_runtime.h>
#include <cstdint>

#define B_  16
#define NC_ 10
#define H_  6
#define C_  384
#define HD_ 64
#define T_  197
#define N_  196
#define BH_ (B_*H_)
#define CH_ (NC_*H_)
#define SCALE_ 0.125f

__device__ float g_n1 [26*C_];
__device__ float g_n2x[B_*N_*C_];
__device__ float g_n2a[NC_*N_*C_];
__device__ float g_qv [NC_*2*C_];
__device__ float g_k  [B_*C_];
__device__ float g_attn[B_*CH_];
__device__ float g_ctx[B_*C_];
__device__ float g_qh [BH_*N_*HD_];
__device__ float g_q2 [BH_*N_*HD_];
__device__ float g_vr [BH_*N_*HD_];
__device__ float g_kh [CH_*N_*HD_];
__device__ float g_k2 [CH_*N_*HD_];
__device__ float g_tmp[BH_*N_*N_];
__device__ float g_rectH[B_*N_*C_];
__device__ float g_xx [B_*T_*C_];
__device__ float g_hdn[B_*T_*C_];
__device__ float g_h1 [B_*T_*4*C_];

__device__ __forceinline__ float to_tf32(float x) {
    uint32_t u;
    asm("cvt.rna.tf32.f32 %0, %1;" : "=r"(u) : "f"(x));
    return __uint_as_float(u);
}
#define U32(x) __float_as_uint(x)

__device__ __forceinline__ void mma8(float* c, uint32_t a0, uint32_t a1, uint32_t a2, uint32_t a3,
                                     uint32_t b0, uint32_t b1)
{
    asm volatile("mma.sync.aligned.m16n8k8.row.col.f32.tf32.tf32.f32 "
                 "{%0,%1,%2,%3},{%4,%5,%6,%7},{%8,%9},{%0,%1,%2,%3};\n"
                 : "+f"(c[0]), "+f"(c[1]), "+f"(c[2]), "+f"(c[3])
                 : "r"(a0), "r"(a1), "r"(a2), "r"(a3), "r"(b0), "r"(b1));
}

// bf16 mma m16n8k16 (fp32 accumulate)
__device__ __forceinline__ void mma16b(float* c, uint32_t a0, uint32_t a1, uint32_t a2, uint32_t a3,
                                       uint32_t b0, uint32_t b1)
{
    asm volatile("mma.sync.aligned.m16n8k16.row.col.f32.bf16.bf16.f32 "
                 "{%0,%1,%2,%3},{%4,%5,%6,%7},{%8,%9},{%0,%1,%2,%3};\n"
                 : "+f"(c[0]), "+f"(c[1]), "+f"(c[2]), "+f"(c[3])
                 : "r"(a0), "r"(a1), "r"(a2), "r"(a3), "r"(b0), "r"(b1));
}

// pack (lo, hi) floats into bf16x2 (lo in low half)
__device__ __forceinline__ uint32_t pack_bf2(float lo, float hi) {
    uint32_t d;
    asm("cvt.rn.bf16x2.f32 %0, %1, %2;" : "=r"(d) : "f"(hi), "f"(lo));
    return d;
}

__device__ __forceinline__ void cp16(uint32_t dst, const void* src, bool p) {
    int sz = p ? 16 : 0;
    asm volatile("cp.async.cg.shared.global [%0], [%1], 16, %2;" :: "r"(dst), "l"(src), "r"(sz));
}

__device__ __forceinline__ float gelu_f(float x) {
    return 0.5f * x * (1.f + erff(x * 0.7071067811865475f));
}

// ---------------- LayerNorm ----------------
__global__ void ln_kernel(const float* __restrict__ in, float* __restrict__ out,
                          const float* __restrict__ g, const float* __restrict__ bt,
                          int rows, int inner, long outer_stride, long inner_stride)
{
    int row = blockIdx.x;
    if (row >= rows) return;
    const float* src = in + (long)(row / inner) * outer_stride + (long)(row % inner) * inner_stride;
    int t = threadIdx.x;
    float v[3]; float s = 0.f;
#pragma unroll
    for (int i = 0; i < 3; i++) { v[i] = src[t + i*128]; s += v[i]; }
    __shared__ float red[4];
#pragma unroll
    for (int o = 16; o > 0; o >>= 1) s += __shfl_xor_sync(0xffffffffu, s, o);
    if ((t & 31) == 0) red[t >> 5] = s;
    __syncthreads();
    float mean = (red[0] + red[1] + red[2] + red[3]) * (1.f/384.f);
    float q = 0.f;
#pragma unroll
    for (int i = 0; i < 3; i++) { float d = v[i] - mean; q += d*d; }
#pragma unroll
    for (int o = 16; o > 0; o >>= 1) q += __shfl_xor_sync(0xffffffffu, q, o);
    __syncthreads();
    if ((t & 31) == 0) red[t >> 5] = q;
    __syncthreads();
    float var = (red[0] + red[1] + red[2] + red[3]) * (1.f/384.f);
    float rs = rsqrtf(var + 1e-5f);
    float* dst = out + (long)row * C_;
#pragma unroll
    for (int i = 0; i < 3; i++) { int c = t + i*128; dst[c] = (v[i] - mean) * rs * g[c] + bt[c]; }
}

// ---------------- small-M row GEMM (cls path), K=384, 4-way ILP ----------------
__global__ __launch_bounds__(256)
void rowgemm(const float* __restrict__ A, const float* __restrict__ W,
             const float* __restrict__ bias, float* __restrict__ out,
             int N, long out_stride)
{
    __shared__ float a_s[384];
    __shared__ float part[128];
    int row = blockIdx.x, cb = blockIdx.y * 128;
    int t = threadIdx.x;
    for (int i = t; i < 384; i += 256) a_s[i] = A[(size_t)row*384 + i];
    __syncthreads();
    int half = t >> 7, c = t & 127;
    int base = half * 192;
    float s0 = 0.f, s1 = 0.f, s2 = 0.f, s3 = 0.f;
    const float* Wp = W + (size_t)base*N + cb + c;
#pragma unroll 8
    for (int k = 0; k < 192; k += 4) {
        s0 += a_s[base+k]   * Wp[(size_t)(k)*N];
        s1 += a_s[base+k+1] * Wp[(size_t)(k+1)*N];
        s2 += a_s[base+k+2] * Wp[(size_t)(k+2)*N];
        s3 += a_s[base+k+3] * Wp[(size_t)(k+3)*N];
    }
    float s = (s0 + s1) + (s2 + s3);
    if (half) part[c] = s;
    __syncthreads();
    if (!half) {
        float v = s + part[c];
        if (bias) v += bias[cb + c];
        out[(size_t)row*out_stride + cb + c] = v;
    }
}

// ---------------- cls attention ----------------
__global__ void attn_cls_kernel(const float* __restrict__ qv, const float* __restrict__ k,
                                float* __restrict__ attn, float* __restrict__ ctx)
{
    int b = blockIdx.x, t = threadIdx.x;
    __shared__ float sl[CH_];
    if (t < CH_) {
        int n = t / H_, h = t % H_;
        float s = 0.f;
        for (int d = 0; d < HD_; d++) s += qv[n*2*C_ + h*HD_ + d] * k[b*C_ + h*HD_ + d];
        sl[t] = s * SCALE_;
    }
    __syncthreads();
    if (t < H_) {
        float mx = -1e30f;
        for (int n = 0; n < NC_; n++) mx = fmaxf(mx, sl[n*H_ + t]);
        float sum = 0.f;
        for (int n = 0; n < NC_; n++) { float e = expf(sl[n*H_ + t] - mx); sl[n*H_ + t] = e; sum += e; }
        float inv = 1.f / sum;
        for (int n = 0; n < NC_; n++) { sl[n*H_ + t] *= inv; attn[b*CH_ + n*H_ + t] = sl[n*H_ + t]; }
    }
    __syncthreads();
    {
        int h = t >> 6, d = t & 63;
        float s = 0.f;
        for (int n = 0; n < NC_; n++) s += sl[n*H_ + h] * qv[n*2*C_ + C_ + h*HD_ + d];
        ctx[b*C_ + t] = s;
    }
}

// 0: row-major; 1: head-major (tf32-rounded); 2: xx rows 1..196
__device__ __forceinline__ size_t out_map(int mode, int mm, int nn, int N)
{
    if (mode == 0) return (size_t)mm * N + nn;
    if (mode == 1) {
        int bq = mm / N_, n = mm % N_;
        return ((size_t)(bq*H_ + (nn >> 6)) * N_ + n) * HD_ + (nn & 63);
    }
    int bq = mm / N_, n = mm % N_;
    return ((size_t)bq*T_ + 1 + n) * C_ + nn;
}

// ---------------- tf32 GEMM 128x64 tile, batched via grid.z ----------------
__global__ __launch_bounds__(256)
void gemm_tf32(const float* __restrict__ A, const float* __restrict__ W,
               const float* __restrict__ bias, const float* __restrict__ res,
               float* __restrict__ out, int M, int N, int K, int act, int mode,
               long zA, long zB, long zO)
{
    __shared__ float As[16*136];
    __shared__ float Bs[16*72];
    A   += (size_t)blockIdx.z * zA;
    W   += (size_t)blockIdx.z * zB;
    out += (size_t)blockIdx.z * zO;
    int tid = threadIdx.x;
    int lane = tid & 31, warp = tid >> 5;
    int gid = lane >> 2, tig = lane & 3;
    int wm = warp >> 1, wn = warp & 1;
    int m0 = blockIdx.y * 128, n0 = blockIdx.x * 64;
    int arow = tid & 63, akq = tid >> 6;
    int brow = tid >> 4, bcol = (tid & 15) * 4;

    float acc[2][4][4];
#pragma unroll
    for (int t = 0; t < 2; t++)
#pragma unroll
        for (int u = 0; u < 4; u++)
#pragma unroll
            for (int e = 0; e < 4; e++) acc[t][u][e] = 0.f;

    for (int kk0 = 0; kk0 < K; kk0 += 16) {
        __syncthreads();
#pragma unroll
        for (int i = 0; i < 2; i++) {
            int row = arow + i*64;
            float4 v = make_float4(0.f,0.f,0.f,0.f);
            if (m0 + row < M && kk0 + akq*4 + 4 <= K)
                v = *(const float4*)(A + (size_t)(m0+row)*K + kk0 + akq*4);
            As[(akq*4+0)*136 + row] = to_tf32(v.x);
            As[(akq*4+1)*136 + row] = to_tf32(v.y);
            As[(akq*4+2)*136 + row] = to_tf32(v.z);
            As[(akq*4+3)*136 + row] = to_tf32(v.w);
        }
        {
            float4 v = make_float4(0.f,0.f,0.f,0.f);
            if (kk0 + brow < K)
                v = *(const float4*)(W + (size_t)(kk0+brow)*N + n0 + bcol);
            float4 c = make_float4(to_tf32(v.x), to_tf32(v.y), to_tf32(v.z), to_tf32(v.w));
            *(float4*)(Bs + brow*72 + bcol) = c;
        }
        __syncthreads();
#pragma unroll
        for (int ks = 0; ks < 2; ks++) {
            int k = ks*8;
            uint32_t a[2][4];
#pragma unroll
            for (int t = 0; t < 2; t++) {
                int mb = wm*32 + t*16;
                a[t][0] = U32(As[(k+tig)*136 + mb+gid]);
                a[t][1] = U32(As[(k+tig)*136 + mb+gid+8]);
                a[t][2] = U32(As[(k+tig+4)*136 + mb+gid]);
                a[t][3] = U32(As[(k+tig+4)*136 + mb+gid+8]);
            }
#pragma unroll
            for (int u = 0; u < 4; u++) {
                int cb = wn*32 + u*8;
                uint32_t b0 = U32(Bs[(k+tig)*72 + cb+gid]);
                uint32_t b1 = U32(Bs[(k+tig+4)*72 + cb+gid]);
                mma8(acc[0][u], a[0][0],a[0][1],a[0][2],a[0][3], b0,b1);
                mma8(acc[1][u], a[1][0],a[1][1],a[1][2],a[1][3], b0,b1);
            }
        }
    }
#pragma unroll
    for (int t = 0; t < 2; t++) {
#pragma unroll
        for (int u = 0; u < 4; u++) {
            int rb = m0 + wm*32 + t*16 + gid;
            int cb = n0 + wn*32 + u*8 + 2*tig;
#pragma unroll
            for (int e = 0; e < 4; e++) {
                int r = rb + (e >> 1) * 8;
                int c = cb + (e & 1);
                if (r < M) {
                    float v = acc[t][u][e];
                    if (bias) v += bias[c];
                    if (act) v = gelu_f(v);
                    if (mode == 1) v = to_tf32(v);
                    size_t idx = out_map(mode, r, c, N);
                    if (res) v += res[idx];
                    out[idx] = v;
                }
            }
        }
    }
}

// ---------------- fused rectified attention core ----------------
// G1 (tf32): L[n,m] = relu(-S*qh.kh^T)*w2 ; G2 (tf32): R^T[p,m] = relu(S*q2.k2^T)
// G3 (bf16 m16n8k16): tmp[n,p] += L . R
__global__ __launch_bounds__(256, 1)
void fused_attn2(const float* __restrict__ qh, const float* __restrict__ kh,
                 const float* __restrict__ q2, const float* __restrict__ k2,
                 const float* __restrict__ w2all, float* __restrict__ tmp_out)
{
    __shared__ float sm_[8704];
    float* const kbuf0 = sm_;              // [16][68]
    float* const kbuf1 = sm_ + 1088;
    float* const vbuf0 = sm_ + 2176;
    float* const vbuf1 = sm_ + 3264;
    uint32_t* const L2_s  = (uint32_t*)(sm_ + 4352);  // [8][136]  bf16x2 pairs along m
    uint32_t* const Rt2_s = (uint32_t*)(sm_ + 5440);  // [128][12] bf16x2 pairs along m

    int tid = threadIdx.x;
    int lane = tid & 31, warp = tid >> 5;
    int gid = lane >> 2, tig = lane & 3;
    int wm = warp >> 1, wn = warp & 1;

    int bh = blockIdx.z;
    int b = bh / H_, h = bh % H_;
    int n0 = blockIdx.y * 68;
    int p0 = blockIdx.x * 68;

    const float* qh_b = qh + (size_t)bh * N_ * HD_;
    const float* q2_b = q2 + (size_t)bh * N_ * HD_;

    // stage qh tile [128][68], capture A-frags (rows warp*16..+16)
    uint32_t aq[8][4];
    for (int i = tid; i < 2048; i += 256) {
        int r = i >> 4, c4 = (i & 15) * 4;
        *(float4*)(sm_ + r*68 + c4) = *(const float4*)(qh_b + (size_t)(n0+r)*HD_ + c4);
    }
    __syncthreads();
    {
        int rb = warp * 16;
#pragma unroll
        for (int j = 0; j < 8; j++) {
            aq[j][0] = U32(sm_[(rb+gid)*68 + 8*j+tig]);
            aq[j][1] = U32(sm_[(rb+gid+8)*68 + 8*j+tig]);
            aq[j][2] = U32(sm_[(rb+gid)*68 + 8*j+tig+4]);
            aq[j][3] = U32(sm_[(rb+gid+8)*68 + 8*j+tig+4]);
        }
    }
    __syncthreads();
    // stage q2 tile, capture A-frags of q2 (rows = p-strip warp*16..+16)
    uint32_t aq2[8][4];
    for (int i = tid; i < 2048; i += 256) {
        int r = i >> 4, c4 = (i & 15) * 4;
        *(float4*)(sm_ + r*68 + c4) = *(const float4*)(q2_b + (size_t)(p0+r)*HD_ + c4);
    }
    __syncthreads();
    {
        int pb = warp * 16;
#pragma unroll
        for (int j = 0; j < 8; j++) {
            aq2[j][0] = U32(sm_[(pb+gid)*68 + 8*j+tig]);
            aq2[j][1] = U32(sm_[(pb+gid+8)*68 + 8*j+tig]);
            aq2[j][2] = U32(sm_[(pb+gid)*68 + 8*j+tig+4]);
            aq2[j][3] = U32(sm_[(pb+gid+8)*68 + 8*j+tig+4]);
        }
    }
    __syncthreads();

    float acc[2][8][4];
#pragma unroll
    for (int t = 0; t < 2; t++)
#pragma unroll
        for (int u = 0; u < 8; u++)
#pragma unroll
            for (int e = 0; e < 4; e++) acc[t][u][e] = 0.f;

    uint32_t kd0 = (uint32_t)__cvta_generic_to_shared(kbuf0);
    uint32_t kd1 = (uint32_t)__cvta_generic_to_shared(kbuf1);
    uint32_t vd0 = (uint32_t)__cvta_generic_to_shared(vbuf0);
    uint32_t vd1 = (uint32_t)__cvta_generic_to_shared(vbuf1);
    int prow = tid >> 4, pc4 = (tid & 15) * 4;

    {
        const float* kh_c = kh + (size_t)h * N_ * HD_;
        const float* k2_c = k2 + (size_t)h * N_ * HD_;
        cp16(kd0 + (prow*68 + pc4)*4, kh_c + (size_t)prow*HD_ + pc4, true);
        cp16(vd0 + (prow*68 + pc4)*4, k2_c + (size_t)prow*HD_ + pc4, true);
    }
    asm volatile("cp.async.commit_group;" ::: "memory");

    int buf = 0;
    for (int c = 0; c < NC_; c++) {
        float w2c = w2all[b*CH_ + h*NC_ + c];
        for (int mc = 0; mc < 13; mc++) {
            {
                int nc2 = c, nm = mc + 1;
                if (nm == 13) { nm = 0; nc2 = c + 1; }
                if (nc2 < NC_) {
                    const float* kh_c = kh + (size_t)(nc2*H_ + h) * N_ * HD_;
                    const float* k2_c = k2 + (size_t)(nc2*H_ + h) * N_ * HD_;
                    int m = nm*16 + prow;
                    bool ok = m < N_;
                    size_t off = ok ? ((size_t)m*HD_ + pc4) : 0;
                    uint32_t kd = buf ? kd0 : kd1;
                    uint32_t vd = buf ? vd0 : vd1;
                    cp16(kd + (prow*68 + pc4)*4, kh_c + off, ok);
                    cp16(vd + (prow*68 + pc4)*4, k2_c + off, ok);
                }
            }
            asm volatile("cp.async.commit_group;" ::: "memory");
            asm volatile("cp.async.wait_group 1;" ::: "memory");
            __syncthreads();

            const float* KT  = buf ? kbuf1 : kbuf0;
            const float* K2T = buf ? vbuf1 : vbuf0;

            // GEMM-1 (tf32): warp strip of L (n 16 x m 16)
            float lacc[2][4];
#pragma unroll
            for (int t = 0; t < 2; t++)
#pragma unroll
                for (int e = 0; e < 4; e++) lacc[t][e] = 0.f;
#pragma unroll
            for (int j = 0; j < 8; j++) {
#pragma unroll
                for (int t = 0; t < 2; t++) {
                    uint32_t b0 = U32(KT[(8*t+gid)*68 + 8*j+tig]);
                    uint32_t b1 = U32(KT[(8*t+gid)*68 + 8*j+tig+4]);
                    mma8(lacc[t], aq[j][0],aq[j][1],aq[j][2],aq[j][3], b0,b1);
                }
            }
            // GEMM-2 (tf32): warp strip of R^T (p 16 x m 16), A=q2 frags, B=k2
            float racc[2][4];
#pragma unroll
            for (int t = 0; t < 2; t++)
#pragma unroll
                for (int e = 0; e < 4; e++) racc[t][e] = 0.f;
#pragma unroll
            for (int j = 0; j < 8; j++) {
#pragma unroll
                for (int t = 0; t < 2; t++) {
                    uint32_t b0 = U32(K2T[(8*t+gid)*68 + 8*j+tig]);
                    uint32_t b1 = U32(K2T[(8*t+gid)*68 + 8*j+tig+4]);
                    mma8(racc[t], aq2[j][0],aq2[j][1],aq2[j][2],aq2[j][3], b0,b1);
                }
            }
            // store L (bf16x2, pairs along m) and R^T (bf16x2, pairs along m)
            {
                int nr = warp*16 + gid;
                int pb = warp*16;
#pragma unroll
                for (int t = 0; t < 2; t++) {
                    // lacc[t]: rows (gid, gid+8) of n-strip, cols (8t+2tig, +1) of m
                    float l0 = w2c * fmaxf(0.f, -SCALE_*lacc[t][0]);
                    float l1 = w2c * fmaxf(0.f, -SCALE_*lacc[t][1]);
                    float l2 = w2c * fmaxf(0.f, -SCALE_*lacc[t][2]);
                    float l3 = w2c * fmaxf(0.f, -SCALE_*lacc[t][3]);
                    L2_s[(4*t+tig)*136 + nr]     = pack_bf2(l0, l1);
                    L2_s[(4*t+tig)*136 + nr + 8] = pack_bf2(l2, l3);
                    // racc[t]: rows (gid, gid+8) of p-strip, cols (8t+2tig, +1) of m
                    float r0 = fmaxf(0.f, SCALE_*racc[t][0]);
                    float r1 = fmaxf(0.f, SCALE_*racc[t][1]);
                    float r2 = fmaxf(0.f, SCALE_*racc[t][2]);
                    float r3 = fmaxf(0.f, SCALE_*racc[t][3]);
                    Rt2_s[(pb+gid)*12 + 4*t+tig]   = pack_bf2(r0, r1);
                    Rt2_s[(pb+gid+8)*12 + 4*t+tig] = pack_bf2(r2, r3);
                }
            }
            __syncthreads();
            // GEMM-3 (bf16 m16n8k16): acc += L . R  (K=16, single step)
            {
                uint32_t a[2][4];
#pragma unroll
                for (int t = 0; t < 2; t++) {
                    int mb = wm*32 + t*16;
                    a[t][0] = L2_s[tig*136 + mb+gid];
                    a[t][1] = L2_s[tig*136 + mb+gid+8];
                    a[t][2] = L2_s[(tig+4)*136 + mb+gid];
                    a[t][3] = L2_s[(tig+4)*136 + mb+gid+8];
                }
#pragma unroll
                for (int u = 0; u < 8; u++) {
                    int cb = wn*64 + u*8;
                    uint32_t b0 = Rt2_s[(cb+gid)*12 + tig];
                    uint32_t b1 = Rt2_s[(cb+gid)*12 + tig+4];
                    mma16b(acc[0][u], a[0][0],a[0][1],a[0][2],a[0][3], b0,b1);
                    mma16b(acc[1][u], a[1][0],a[1][1],a[1][2],a[1][3], b0,b1);
                }
            }
            buf ^= 1;
        }
    }

    float* o = tmp_out + (size_t)bh * N_ * N_;
#pragma unroll
    for (int t = 0; t < 2; t++) {
#pragma unroll
        for (int u = 0; u < 8; u++) {
            int n = n0 + wm*32 + t*16 + gid;
            int p = p0 + wn*64 + u*8 + 2*tig;
            o[(size_t)n*N_ + p]         = acc[t][u][0];
            o[(size_t)n*N_ + p + 1]     = acc[t][u][1];
            o[(size_t)(n+8)*N_ + p]     = acc[t][u][2];
            o[(size_t)(n+8)*N_ + p + 1] = acc[t][u][3];
        }
    }
}

__global__ void copy_kernel(const float* __restrict__ src, float* __restrict__ dst, int n4)
{
    int i = blockIdx.x * blockDim.x + threadIdx.x;
    if (i < n4) ((float4*)dst)[i] = ((const float4*)src)[i];
}

extern "C" void kernel_launch(void* const* d_in, const int* in_sizes, int n_in,
                              void* d_out, int out_size)
{
    const float* x       = (const float*)d_in[0];
    const float* Wqv     = (const float*)d_in[1];
    const float* Wk      = (const float*)d_in[2];
    const float* Wq_proj = (const float*)d_in[3];
    const float* bq_proj = (const float*)d_in[4];
    const float* Wqk     = (const float*)d_in[5];
    const float* Wqk2    = (const float*)d_in[6];
    const float* Wv      = (const float*)d_in[7];
    const float* Wr_proj = (const float*)d_in[8];
    const float* br_proj = (const float*)d_in[9];
    const float* g1      = (const float*)d_in[10];
    const float* b1      = (const float*)d_in[11];
    const float* g2      = (const float*)d_in[12];
    const float* b2      = (const float*)d_in[13];
    const float* g3      = (const float*)d_in[14];
    const float* b3      = (const float*)d_in[15];
    const float* W1      = (const float*)d_in[16];
    const float* bm1     = (const float*)d_in[17];
    const float* W2      = (const float*)d_in[18];
    const float* bm2     = (const float*)d_in[19];
    float* outp = (float*)d_out;

    float *n1, *n2x, *n2a, *qv, *kb, *attn, *ctx, *qh, *q2, *vrp, *khp, *k2p;
    float *tmp, *rectH, *xx, *hdn, *h1;
    cudaGetSymbolAddress((void**)&n1, g_n1);
    cudaGetSymbolAddress((void**)&n2x, g_n2x);
    cudaGetSymbolAddress((void**)&n2a, g_n2a);
    cudaGetSymbolAddress((void**)&qv, g_qv);
    cudaGetSymbolAddress((void**)&kb, g_k);
    cudaGetSymbolAddress((void**)&attn, g_attn);
    cudaGetSymbolAddress((void**)&ctx, g_ctx);
    cudaGetSymbolAddress((void**)&qh, g_qh);
    cudaGetSymbolAddress((void**)&q2, g_q2);
    cudaGetSymbolAddress((void**)&vrp, g_vr);
    cudaGetSymbolAddress((void**)&khp, g_kh);
    cudaGetSymbolAddress((void**)&k2p, g_k2);
    cudaGetSymbolAddress((void**)&tmp, g_tmp);
    cudaGetSymbolAddress((void**)&rectH, g_rectH);
    cudaGetSymbolAddress((void**)&xx, g_xx);
    cudaGetSymbolAddress((void**)&hdn, g_hdn);
    cudaGetSymbolAddress((void**)&h1, g_h1);

    // 1) LayerNorms
    ln_kernel<<<26, 128>>>(x, n1, g1, b1, 26, 26, 0, (long)T_*C_);
    ln_kernel<<<B_*N_, 128>>>(x + C_, n2x, g2, b2, B_*N_, N_, (long)T_*C_, C_);
    ln_kernel<<<NC_*N_, 128>>>(x + (long)16*T_*C_ + C_, n2a, g2, b2, NC_*N_, N_, (long)T_*C_, C_);

    // 2) cls path (row-parallel small GEMMs)
    rowgemm<<<dim3(NC_, 6), 256>>>(n1 + 16*C_, Wqv, nullptr, qv, 2*C_, 2*C_);
    rowgemm<<<dim3(B_, 3), 256>>>(n1, Wk, nullptr, kb, C_, C_);
    attn_cls_kernel<<<B_, 384>>>(qv, kb, attn, ctx);
    rowgemm<<<dim3(B_, 3), 256>>>(ctx, Wq_proj, bq_proj, xx, C_, (long)T_*C_);

    // 3) head projections (head-major, tf32-rounded outputs)
    dim3 gx(6, 25), ga(6, 16);
    gemm_tf32<<<gx, 256>>>(n2x, Wqk,  nullptr, nullptr, qh,  B_*N_, C_, C_, 0, 1, 0,0,0);
    gemm_tf32<<<gx, 256>>>(n2x, Wqk2, nullptr, nullptr, q2,  B_*N_, C_, C_, 0, 1, 0,0,0);
    gemm_tf32<<<gx, 256>>>(n2x, Wv,   nullptr, nullptr, vrp, B_*N_, C_, C_, 0, 1, 0,0,0);
    gemm_tf32<<<ga, 256>>>(n2a, Wqk,  nullptr, nullptr, khp, NC_*N_, C_, C_, 0, 1, 0,0,0);
    gemm_tf32<<<ga, 256>>>(n2a, Wqk2, nullptr, nullptr, k2p, NC_*N_, C_, C_, 0, 1, 0,0,0);

    // 4) fused rectified attention core
    dim3 gf(2, 2, BH_);
    fused_attn2<<<gf, 256>>>(qh, khp, q2, k2p, attn, tmp);

    // 5) rect = tmp @ vr, batched over bh (K=196, guarded)
    dim3 grc(1, 2, BH_);
    gemm_tf32<<<grc, 256>>>(tmp, vrp, nullptr, nullptr, rectH, N_, HD_, N_, 0, 0,
                            (long)N_*N_, (long)N_*HD_, (long)N_*HD_);

    // 6) rect projection + residual -> xx rows 1..196
    gemm_tf32<<<gx, 256>>>(rectH, Wr_proj, br_proj, x, xx, B_*N_, C_, C_, 0, 2, 0,0,0);

    // 7) MLP
    ln_kernel<<<B_*T_, 128>>>(xx, hdn, g3, b3, B_*T_, B_*T_, 0, C_);
    dim3 gm1(24, 25), gm2(6, 25);
    gemm_tf32<<<gm1, 256>>>(hdn, W1, bm1, nullptr, h1, B_*T_, 4*C_, C_, 1, 0, 0,0,0);
    gemm_tf32<<<gm2, 256>>>(h1, W2, bm2, xx, outp, B_*T_, C_, 4*C_, 0, 0, 0,0,0);

    // 8) anchors pass-through
    int n4 = NC_*T_*C_/4;
    copy_kernel<<<(n4 + 255)/256, 256>>>(x + (long)16*T_*C_, outp + (long)16*T_*C_, n4);
}

// round 8
// speedup vs baseline: 1.5858x; 1.1458x over previous
#include <cuda_runtime.h>
#include <cuda_fp16.h>
#include <cstdint>

#define B_  16
#define NC_ 10
#define H_  6
#define C_  384
#define HD_ 64
#define T_  197
#define N_  196
#define BH_ (B_*H_)
#define CH_ (NC_*H_)
#define SCALE_ 0.125f

__device__ float g_n1 [26*C_];
__device__ float g_n2x[B_*N_*C_];
__device__ float g_n2a[NC_*N_*C_];
__device__ float g_qv [NC_*2*C_];
__device__ float g_k  [B_*C_];
__device__ float g_attn[B_*CH_];
__device__ float g_ctx[B_*C_];
__device__ __half g_qh_h[BH_*N_*HD_];
__device__ __half g_q2_h[BH_*N_*HD_];
__device__ __half g_kh_h[CH_*N_*HD_];
__device__ __half g_k2_h[CH_*N_*HD_];
__device__ float g_vr [BH_*N_*HD_];
__device__ float g_tmp[BH_*N_*N_];
__device__ float g_rectH[B_*N_*C_];
__device__ float g_xx [B_*T_*C_];
__device__ float g_hdn[B_*T_*C_];
__device__ float g_h1 [B_*T_*4*C_];

__device__ __forceinline__ float to_tf32(float x) {
    uint32_t u;
    asm("cvt.rna.tf32.f32 %0, %1;" : "=r"(u) : "f"(x));
    return __uint_as_float(u);
}
#define U32(x) __float_as_uint(x)

__device__ __forceinline__ void mma8(float* c, uint32_t a0, uint32_t a1, uint32_t a2, uint32_t a3,
                                     uint32_t b0, uint32_t b1)
{
    asm volatile("mma.sync.aligned.m16n8k8.row.col.f32.tf32.tf32.f32 "
                 "{%0,%1,%2,%3},{%4,%5,%6,%7},{%8,%9},{%0,%1,%2,%3};\n"
                 : "+f"(c[0]), "+f"(c[1]), "+f"(c[2]), "+f"(c[3])
                 : "r"(a0), "r"(a1), "r"(a2), "r"(a3), "r"(b0), "r"(b1));
}

// fp16 mma m16n8k16 (fp32 accumulate)
__device__ __forceinline__ void mma16h(float* c, uint32_t a0, uint32_t a1, uint32_t a2, uint32_t a3,
                                       uint32_t b0, uint32_t b1)
{
    asm volatile("mma.sync.aligned.m16n8k16.row.col.f32.f16.f16.f32 "
                 "{%0,%1,%2,%3},{%4,%5,%6,%7},{%8,%9},{%0,%1,%2,%3};\n"
                 : "+f"(c[0]), "+f"(c[1]), "+f"(c[2]), "+f"(c[3])
                 : "r"(a0), "r"(a1), "r"(a2), "r"(a3), "r"(b0), "r"(b1));
}

// pack (lo, hi) floats into f16x2 (lo in low half)
__device__ __forceinline__ uint32_t pack_hf2(float lo, float hi) {
    uint32_t d;
    asm("cvt.rn.f16x2.f32 %0, %1, %2;" : "=r"(d) : "f"(hi), "f"(lo));
    return d;
}

__device__ __forceinline__ void cp16(uint32_t dst, const void* src, bool p) {
    int sz = p ? 16 : 0;
    asm volatile("cp.async.cg.shared.global [%0], [%1], 16, %2;" :: "r"(dst), "l"(src), "r"(sz));
}

__device__ __forceinline__ float gelu_f(float x) {
    return 0.5f * x * (1.f + erff(x * 0.7071067811865475f));
}

// ---------------- LayerNorm ----------------
__global__ void ln_kernel(const float* __restrict__ in, float* __restrict__ out,
                          const float* __restrict__ g, const float* __restrict__ bt,
                          int rows, int inner, long outer_stride, long inner_stride)
{
    int row = blockIdx.x;
    if (row >= rows) return;
    const float* src = in + (long)(row / inner) * outer_stride + (long)(row % inner) * inner_stride;
    int t = threadIdx.x;
    float v[3]; float s = 0.f;
#pragma unroll
    for (int i = 0; i < 3; i++) { v[i] = src[t + i*128]; s += v[i]; }
    __shared__ float red[4];
#pragma unroll
    for (int o = 16; o > 0; o >>= 1) s += __shfl_xor_sync(0xffffffffu, s, o);
    if ((t & 31) == 0) red[t >> 5] = s;
    __syncthreads();
    float mean = (red[0] + red[1] + red[2] + red[3]) * (1.f/384.f);
    float q = 0.f;
#pragma unroll
    for (int i = 0; i < 3; i++) { float d = v[i] - mean; q += d*d; }
#pragma unroll
    for (int o = 16; o > 0; o >>= 1) q += __shfl_xor_sync(0xffffffffu, q, o);
    __syncthreads();
    if ((t & 31) == 0) red[t >> 5] = q;
    __syncthreads();
    float var = (red[0] + red[1] + red[2] + red[3]) * (1.f/384.f);
    float rs = rsqrtf(var + 1e-5f);
    float* dst = out + (long)row * C_;
#pragma unroll
    for (int i = 0; i < 3; i++) { int c = t + i*128; dst[c] = (v[i] - mean) * rs * g[c] + bt[c]; }
}

// ---------------- small-M row GEMM (cls path), K=384, 4-way K-split ----------------
__global__ __launch_bounds__(256)
void rowgemm(const float* __restrict__ A, const float* __restrict__ W,
             const float* __restrict__ bias, float* __restrict__ out,
             int N, long out_stride)
{
    __shared__ float a_s[384];
    __shared__ float part[256];
    int row = blockIdx.x, cb = blockIdx.y * 64;
    int t = threadIdx.x;
    for (int i = t; i < 384; i += 256) a_s[i] = A[(size_t)row*384 + i];
    __syncthreads();
    int col = t & 63, sp = t >> 6;
    int base = sp * 96;
    float s0 = 0.f, s1 = 0.f;
    const float* Wp = W + (size_t)base*N + cb + col;
#pragma unroll 8
    for (int k = 0; k < 96; k += 2) {
        s0 += a_s[base+k]   * Wp[(size_t)(k)*N];
        s1 += a_s[base+k+1] * Wp[(size_t)(k+1)*N];
    }
    part[t] = s0 + s1;
    __syncthreads();
    if (t < 64) {
        float v = part[t] + part[64+t] + part[128+t] + part[192+t];
        if (bias) v += bias[cb + t];
        out[(size_t)row*out_stride + cb + t] = v;
    }
}

// ---------------- cls attention ----------------
__global__ void attn_cls_kernel(const float* __restrict__ qv, const float* __restrict__ k,
                                float* __restrict__ attn, float* __restrict__ ctx)
{
    int b = blockIdx.x, t = threadIdx.x;
    __shared__ float sl[CH_];
    if (t < CH_) {
        int n = t / H_, h = t % H_;
        float s = 0.f;
        for (int d = 0; d < HD_; d++) s += qv[n*2*C_ + h*HD_ + d] * k[b*C_ + h*HD_ + d];
        sl[t] = s * SCALE_;
    }
    __syncthreads();
    if (t < H_) {
        float mx = -1e30f;
        for (int n = 0; n < NC_; n++) mx = fmaxf(mx, sl[n*H_ + t]);
        float sum = 0.f;
        for (int n = 0; n < NC_; n++) { float e = expf(sl[n*H_ + t] - mx); sl[n*H_ + t] = e; sum += e; }
        float inv = 1.f / sum;
        for (int n = 0; n < NC_; n++) { sl[n*H_ + t] *= inv; attn[b*CH_ + n*H_ + t] = sl[n*H_ + t]; }
    }
    __syncthreads();
    {
        int h = t >> 6, d = t & 63;
        float s = 0.f;
        for (int n = 0; n < NC_; n++) s += sl[n*H_ + h] * qv[n*2*C_ + C_ + h*HD_ + d];
        ctx[b*C_ + t] = s;
    }
}

// 0: row-major; 1: head-major; 2: xx rows 1..196
__device__ __forceinline__ size_t out_map(int mode, int mm, int nn, int N)
{
    if (mode == 0) return (size_t)mm * N + nn;
    if (mode == 1) {
        int bq = mm / N_, n = mm % N_;
        return ((size_t)(bq*H_ + (nn >> 6)) * N_ + n) * HD_ + (nn & 63);
    }
    int bq = mm / N_, n = mm % N_;
    return ((size_t)bq*T_ + 1 + n) * C_ + nn;
}

// ---------------- tf32 GEMM 128x64 tile, batched via grid.z, optional fp16 out ----
__global__ __launch_bounds__(256)
void gemm_tf32(const float* __restrict__ A, const float* __restrict__ W,
               const float* __restrict__ bias, const float* __restrict__ res,
               float* __restrict__ out, int M, int N, int K, int act, int mode, int h16,
               long zA, long zB, long zO)
{
    __shared__ float As[16*136];
    __shared__ float Bs[16*72];
    A   += (size_t)blockIdx.z * zA;
    W   += (size_t)blockIdx.z * zB;
    int tid = threadIdx.x;
    int lane = tid & 31, warp = tid >> 5;
    int gid = lane >> 2, tig = lane & 3;
    int wm = warp >> 1, wn = warp & 1;
    int m0 = blockIdx.y * 128, n0 = blockIdx.x * 64;
    int arow = tid & 63, akq = tid >> 6;
    int brow = tid >> 4, bcol = (tid & 15) * 4;

    float acc[2][4][4];
#pragma unroll
    for (int t = 0; t < 2; t++)
#pragma unroll
        for (int u = 0; u < 4; u++)
#pragma unroll
            for (int e = 0; e < 4; e++) acc[t][u][e] = 0.f;

    for (int kk0 = 0; kk0 < K; kk0 += 16) {
        __syncthreads();
#pragma unroll
        for (int i = 0; i < 2; i++) {
            int row = arow + i*64;
            float4 v = make_float4(0.f,0.f,0.f,0.f);
            if (m0 + row < M && kk0 + akq*4 + 4 <= K)
                v = *(const float4*)(A + (size_t)(m0+row)*K + kk0 + akq*4);
            As[(akq*4+0)*136 + row] = to_tf32(v.x);
            As[(akq*4+1)*136 + row] = to_tf32(v.y);
            As[(akq*4+2)*136 + row] = to_tf32(v.z);
            As[(akq*4+3)*136 + row] = to_tf32(v.w);
        }
        {
            float4 v = make_float4(0.f,0.f,0.f,0.f);
            if (kk0 + brow < K)
                v = *(const float4*)(W + (size_t)(kk0+brow)*N + n0 + bcol);
            float4 c = make_float4(to_tf32(v.x), to_tf32(v.y), to_tf32(v.z), to_tf32(v.w));
            *(float4*)(Bs + brow*72 + bcol) = c;
        }
        __syncthreads();
#pragma unroll
        for (int ks = 0; ks < 2; ks++) {
            int k = ks*8;
            uint32_t a[2][4];
#pragma unroll
            for (int t = 0; t < 2; t++) {
                int mb = wm*32 + t*16;
                a[t][0] = U32(As[(k+tig)*136 + mb+gid]);
                a[t][1] = U32(As[(k+tig)*136 + mb+gid+8]);
                a[t][2] = U32(As[(k+tig+4)*136 + mb+gid]);
                a[t][3] = U32(As[(k+tig+4)*136 + mb+gid+8]);
            }
#pragma unroll
            for (int u = 0; u < 4; u++) {
                int cb = wn*32 + u*8;
                uint32_t b0 = U32(Bs[(k+tig)*72 + cb+gid]);
                uint32_t b1 = U32(Bs[(k+tig+4)*72 + cb+gid]);
                mma8(acc[0][u], a[0][0],a[0][1],a[0][2],a[0][3], b0,b1);
                mma8(acc[1][u], a[1][0],a[1][1],a[1][2],a[1][3], b0,b1);
            }
        }
    }
#pragma unroll
    for (int t = 0; t < 2; t++) {
#pragma unroll
        for (int u = 0; u < 4; u++) {
            int rb = m0 + wm*32 + t*16 + gid;
            int cb = n0 + wn*32 + u*8 + 2*tig;
#pragma unroll
            for (int e = 0; e < 4; e++) {
                int r = rb + (e >> 1) * 8;
                int c = cb + (e & 1);
                if (r < M) {
                    float v = acc[t][u][e];
                    if (bias) v += bias[c];
                    if (act) v = gelu_f(v);
                    size_t idx = out_map(mode, r, c, N) + (size_t)blockIdx.z * zO;
                    if (h16) {
                        ((__half*)out)[idx] = __float2half(v);
                    } else {
                        if (mode == 1) v = to_tf32(v);
                        if (res) v += res[idx];
                        out[idx] = v;
                    }
                }
            }
        }
    }
}

// ---------------- fused rectified attention core (all-fp16 operands) ----------------
// G1: L[n,m] = relu(-S*qh.kh^T)*w2 ; G2: R^T[p,m] = relu(S*q2.k2^T) ; G3: tmp += L.R
__global__ __launch_bounds__(256, 1)
void fused_attn3(const __half* __restrict__ qh, const __half* __restrict__ kh,
                 const __half* __restrict__ q2, const __half* __restrict__ k2,
                 const float* __restrict__ w2all, float* __restrict__ tmp_out)
{
    __shared__ __align__(16) unsigned char smx[19712];
    __half* const stage = (__half*)smx;              // [128][72] during staging
    __half* const kbuf0 = (__half*)smx;              // [16][72]
    __half* const kbuf1 = kbuf0 + 16*72;
    __half* const vbuf0 = kbuf1 + 16*72;
    __half* const vbuf1 = vbuf0 + 16*72;
    uint32_t* const L2_s  = (uint32_t*)(smx + 9216);   // [8][136] f16x2 pairs along m
    uint32_t* const Rt2_s = (uint32_t*)(smx + 13568);  // [128][12] f16x2 pairs along m

    int tid = threadIdx.x;
    int lane = tid & 31, warp = tid >> 5;
    int gid = lane >> 2, tig = lane & 3;
    int wm = warp >> 1, wn = warp & 1;

    int bh = blockIdx.z;
    int b = bh / H_, h = bh % H_;
    int n0 = blockIdx.y * 68;
    int p0 = blockIdx.x * 68;

    const __half* qh_b = qh + (size_t)bh * N_ * HD_;
    const __half* q2_b = q2 + (size_t)bh * N_ * HD_;

    // stage qh tile [128][72] halves, capture A-frags (rows warp*16..+16)
    uint32_t aq[4][4];
    for (int i = tid; i < 1024; i += 256) {
        int r = i >> 3, c8 = (i & 7) * 8;
        *(float4*)(stage + r*72 + c8) = *(const float4*)(qh_b + (size_t)(n0+r)*HD_ + c8);
    }
    __syncthreads();
    {
        int rb = warp * 16;
#pragma unroll
        for (int j = 0; j < 4; j++) {
            aq[j][0] = *(const uint32_t*)(stage + (rb+gid)*72   + 16*j + 2*tig);
            aq[j][1] = *(const uint32_t*)(stage + (rb+gid+8)*72 + 16*j + 2*tig);
            aq[j][2] = *(const uint32_t*)(stage + (rb+gid)*72   + 16*j + 2*tig + 8);
            aq[j][3] = *(const uint32_t*)(stage + (rb+gid+8)*72 + 16*j + 2*tig + 8);
        }
    }
    __syncthreads();
    // stage q2 tile, capture A-frags (rows = p-strip warp*16..+16)
    uint32_t aq2[4][4];
    for (int i = tid; i < 1024; i += 256) {
        int r = i >> 3, c8 = (i & 7) * 8;
        *(float4*)(stage + r*72 + c8) = *(const float4*)(q2_b + (size_t)(p0+r)*HD_ + c8);
    }
    __syncthreads();
    {
        int pb = warp * 16;
#pragma unroll
        for (int j = 0; j < 4; j++) {
            aq2[j][0] = *(const uint32_t*)(stage + (pb+gid)*72   + 16*j + 2*tig);
            aq2[j][1] = *(const uint32_t*)(stage + (pb+gid+8)*72 + 16*j + 2*tig);
            aq2[j][2] = *(const uint32_t*)(stage + (pb+gid)*72   + 16*j + 2*tig + 8);
            aq2[j][3] = *(const uint32_t*)(stage + (pb+gid+8)*72 + 16*j + 2*tig + 8);
        }
    }
    __syncthreads();

    float acc[2][8][4];
#pragma unroll
    for (int t = 0; t < 2; t++)
#pragma unroll
        for (int u = 0; u < 8; u++)
#pragma unroll
            for (int e = 0; e < 4; e++) acc[t][u][e] = 0.f;

    uint32_t kd0 = (uint32_t)__cvta_generic_to_shared(kbuf0);
    uint32_t kd1 = (uint32_t)__cvta_generic_to_shared(kbuf1);
    uint32_t vd0 = (uint32_t)__cvta_generic_to_shared(vbuf0);
    uint32_t vd1 = (uint32_t)__cvta_generic_to_shared(vbuf1);

    // chunk staging: threads 0-127 -> kh, 128-255 -> k2; one 16B chunk each
    int op  = tid >> 7;
    int pr  = (tid & 127) >> 3;
    int pc8 = (tid & 7) * 8;

    {
        const __half* src = (op ? k2 : kh) + (size_t)h * N_ * HD_ + (size_t)pr*HD_ + pc8;
        uint32_t d = (op ? vd0 : kd0) + (pr*72 + pc8)*2;
        cp16(d, src, true);
    }
    asm volatile("cp.async.commit_group;" ::: "memory");

    int buf = 0;
    for (int c = 0; c < NC_; c++) {
        float w2c = w2all[b*CH_ + h*NC_ + c];
        for (int mc = 0; mc < 13; mc++) {
            {
                int nc2 = c, nm = mc + 1;
                if (nm == 13) { nm = 0; nc2 = c + 1; }
                if (nc2 < NC_) {
                    int m = nm*16 + pr;
                    bool ok = m < N_;
                    const __half* basep = (op ? k2 : kh) + (size_t)(nc2*H_ + h) * N_ * HD_;
                    const __half* src = basep + (ok ? ((size_t)m*HD_ + pc8) : 0);
                    uint32_t d = (op ? (buf ? vd0 : vd1) : (buf ? kd0 : kd1)) + (pr*72 + pc8)*2;
                    cp16(d, src, ok);
                }
            }
            asm volatile("cp.async.commit_group;" ::: "memory");
            asm volatile("cp.async.wait_group 1;" ::: "memory");
            __syncthreads();

            const __half* KT  = buf ? kbuf1 : kbuf0;
            const __half* K2T = buf ? vbuf1 : vbuf0;

            // GEMM-1 (fp16): warp strip of L (n 16 x m 16)
            float lacc[2][4];
#pragma unroll
            for (int t = 0; t < 2; t++)
#pragma unroll
                for (int e = 0; e < 4; e++) lacc[t][e] = 0.f;
#pragma unroll
            for (int j = 0; j < 4; j++) {
                uint32_t b0lo = *(const uint32_t*)(KT + gid*72     + 16*j + 2*tig);
                uint32_t b1lo = *(const uint32_t*)(KT + gid*72     + 16*j + 2*tig + 8);
                uint32_t b0hi = *(const uint32_t*)(KT + (gid+8)*72 + 16*j + 2*tig);
                uint32_t b1hi = *(const uint32_t*)(KT + (gid+8)*72 + 16*j + 2*tig + 8);
                mma16h(lacc[0], aq[j][0],aq[j][1],aq[j][2],aq[j][3], b0lo,b1lo);
                mma16h(lacc[1], aq[j][0],aq[j][1],aq[j][2],aq[j][3], b0hi,b1hi);
            }
            // GEMM-2 (fp16): warp strip of R^T (p 16 x m 16)
            float racc[2][4];
#pragma unroll
            for (int t = 0; t < 2; t++)
#pragma unroll
                for (int e = 0; e < 4; e++) racc[t][e] = 0.f;
#pragma unroll
            for (int j = 0; j < 4; j++) {
                uint32_t b0lo = *(const uint32_t*)(K2T + gid*72     + 16*j + 2*tig);
                uint32_t b1lo = *(const uint32_t*)(K2T + gid*72     + 16*j + 2*tig + 8);
                uint32_t b0hi = *(const uint32_t*)(K2T + (gid+8)*72 + 16*j + 2*tig);
                uint32_t b1hi = *(const uint32_t*)(K2T + (gid+8)*72 + 16*j + 2*tig + 8);
                mma16h(racc[0], aq2[j][0],aq2[j][1],aq2[j][2],aq2[j][3], b0lo,b1lo);
                mma16h(racc[1], aq2[j][0],aq2[j][1],aq2[j][2],aq2[j][3], b0hi,b1hi);
            }
            // store L and R^T as f16x2 pairs along m
            {
                int nr = warp*16 + gid;
                int pb = warp*16;
#pragma unroll
                for (int t = 0; t < 2; t++) {
                    float l0 = w2c * fmaxf(0.f, -SCALE_*lacc[t][0]);
                    float l1 = w2c * fmaxf(0.f, -SCALE_*lacc[t][1]);
                    float l2 = w2c * fmaxf(0.f, -SCALE_*lacc[t][2]);
                    float l3 = w2c * fmaxf(0.f, -SCALE_*lacc[t][3]);
                    L2_s[(4*t+tig)*136 + nr]     = pack_hf2(l0, l1);
                    L2_s[(4*t+tig)*136 + nr + 8] = pack_hf2(l2, l3);
                    float r0 = fmaxf(0.f, SCALE_*racc[t][0]);
                    float r1 = fmaxf(0.f, SCALE_*racc[t][1]);
                    float r2 = fmaxf(0.f, SCALE_*racc[t][2]);
                    float r3 = fmaxf(0.f, SCALE_*racc[t][3]);
                    Rt2_s[(pb+gid)*12 + 4*t+tig]   = pack_hf2(r0, r1);
                    Rt2_s[(pb+gid+8)*12 + 4*t+tig] = pack_hf2(r2, r3);
                }
            }
            __syncthreads();
            // GEMM-3 (fp16 m16n8k16): acc += L . R  (K=16)
            {
                uint32_t a[2][4];
#pragma unroll
                for (int t = 0; t < 2; t++) {
                    int mb = wm*32 + t*16;
                    a[t][0] = L2_s[tig*136 + mb+gid];
                    a[t][1] = L2_s[tig*136 + mb+gid+8];
                    a[t][2] = L2_s[(tig+4)*136 + mb+gid];
                    a[t][3] = L2_s[(tig+4)*136 + mb+gid+8];
                }
#pragma unroll
                for (int u = 0; u < 8; u++) {
                    int cb = wn*64 + u*8;
                    uint32_t b0 = Rt2_s[(cb+gid)*12 + tig];
                    uint32_t b1 = Rt2_s[(cb+gid)*12 + tig+4];
                    mma16h(acc[0][u], a[0][0],a[0][1],a[0][2],a[0][3], b0,b1);
                    mma16h(acc[1][u], a[1][0],a[1][1],a[1][2],a[1][3], b0,b1);
                }
            }
            buf ^= 1;
        }
    }

    float* o = tmp_out + (size_t)bh * N_ * N_;
#pragma unroll
    for (int t = 0; t < 2; t++) {
#pragma unroll
        for (int u = 0; u < 8; u++) {
            int n = n0 + wm*32 + t*16 + gid;
            int p = p0 + wn*64 + u*8 + 2*tig;
            o[(size_t)n*N_ + p]         = acc[t][u][0];
            o[(size_t)n*N_ + p + 1]     = acc[t][u][1];
            o[(size_t)(n+8)*N_ + p]     = acc[t][u][2];
            o[(size_t)(n+8)*N_ + p + 1] = acc[t][u][3];
        }
    }
}

__global__ void copy_kernel(const float* __restrict__ src, float* __restrict__ dst, int n4)
{
    int i = blockIdx.x * blockDim.x + threadIdx.x;
    if (i < n4) ((float4*)dst)[i] = ((const float4*)src)[i];
}

extern "C" void kernel_launch(void* const* d_in, const int* in_sizes, int n_in,
                              void* d_out, int out_size)
{
    const float* x       = (const float*)d_in[0];
    const float* Wqv     = (const float*)d_in[1];
    const float* Wk      = (const float*)d_in[2];
    const float* Wq_proj = (const float*)d_in[3];
    const float* bq_proj = (const float*)d_in[4];
    const float* Wqk     = (const float*)d_in[5];
    const float* Wqk2    = (const float*)d_in[6];
    const float* Wv      = (const float*)d_in[7];
    const float* Wr_proj = (const float*)d_in[8];
    const float* br_proj = (const float*)d_in[9];
    const float* g1      = (const float*)d_in[10];
    const float* b1      = (const float*)d_in[11];
    const float* g2      = (const float*)d_in[12];
    const float* b2      = (const float*)d_in[13];
    const float* g3      = (const float*)d_in[14];
    const float* b3      = (const float*)d_in[15];
    const float* W1      = (const float*)d_in[16];
    const float* bm1     = (const float*)d_in[17];
    const float* W2      = (const float*)d_in[18];
    const float* bm2     = (const float*)d_in[19];
    float* outp = (float*)d_out;

    float *n1, *n2x, *n2a, *qv, *kb, *attn, *ctx, *vrp, *tmp, *rectH, *xx, *hdn, *h1;
    __half *qh, *q2, *kh, *k2;
    cudaGetSymbolAddress((void**)&n1, g_n1);
    cudaGetSymbolAddress((void**)&n2x, g_n2x);
    cudaGetSymbolAddress((void**)&n2a, g_n2a);
    cudaGetSymbolAddress((void**)&qv, g_qv);
    cudaGetSymbolAddress((void**)&kb, g_k);
    cudaGetSymbolAddress((void**)&attn, g_attn);
    cudaGetSymbolAddress((void**)&ctx, g_ctx);
    cudaGetSymbolAddress((void**)&qh, g_qh_h);
    cudaGetSymbolAddress((void**)&q2, g_q2_h);
    cudaGetSymbolAddress((void**)&kh, g_kh_h);
    cudaGetSymbolAddress((void**)&k2, g_k2_h);
    cudaGetSymbolAddress((void**)&vrp, g_vr);
    cudaGetSymbolAddress((void**)&tmp, g_tmp);
    cudaGetSymbolAddress((void**)&rectH, g_rectH);
    cudaGetSymbolAddress((void**)&xx, g_xx);
    cudaGetSymbolAddress((void**)&hdn, g_hdn);
    cudaGetSymbolAddress((void**)&h1, g_h1);

    // 1) LayerNorms
    ln_kernel<<<26, 128>>>(x, n1, g1, b1, 26, 26, 0, (long)T_*C_);
    ln_kernel<<<B_*N_, 128>>>(x + C_, n2x, g2, b2, B_*N_, N_, (long)T_*C_, C_);
    ln_kernel<<<NC_*N_, 128>>>(x + (long)16*T_*C_ + C_, n2a, g2, b2, NC_*N_, N_, (long)T_*C_, C_);

    // 2) cls path (row-parallel small GEMMs, 4-way K-split)
    rowgemm<<<dim3(NC_, 12), 256>>>(n1 + 16*C_, Wqv, nullptr, qv, 2*C_, 2*C_);
    rowgemm<<<dim3(B_, 6), 256>>>(n1, Wk, nullptr, kb, C_, C_);
    attn_cls_kernel<<<B_, 384>>>(qv, kb, attn, ctx);
    rowgemm<<<dim3(B_, 6), 256>>>(ctx, Wq_proj, bq_proj, xx, C_, (long)T_*C_);

    // 3) head projections (head-major; qh/q2/kh/k2 in fp16, vr in fp32)
    dim3 gx(6, 25), ga(6, 16);
    gemm_tf32<<<gx, 256>>>(n2x, Wqk,  nullptr, nullptr, (float*)qh, B_*N_, C_, C_, 0, 1, 1, 0,0,0);
    gemm_tf32<<<gx, 256>>>(n2x, Wqk2, nullptr, nullptr, (float*)q2, B_*N_, C_, C_, 0, 1, 1, 0,0,0);
    gemm_tf32<<<gx, 256>>>(n2x, Wv,   nullptr, nullptr, vrp,        B_*N_, C_, C_, 0, 1, 0, 0,0,0);
    gemm_tf32<<<ga, 256>>>(n2a, Wqk,  nullptr, nullptr, (float*)kh, NC_*N_, C_, C_, 0, 1, 1, 0,0,0);
    gemm_tf32<<<ga, 256>>>(n2a, Wqk2, nullptr, nullptr, (float*)k2, NC_*N_, C_, C_, 0, 1, 1, 0,0,0);

    // 4) fused rectified attention core (fp16 operands, fp32 accum)
    dim3 gf(2, 2, BH_);
    fused_attn3<<<gf, 256>>>(qh, kh, q2, k2, attn, tmp);

    // 5) rect = tmp @ vr, batched over bh (K=196, guarded)
    dim3 grc(1, 2, BH_);
    gemm_tf32<<<grc, 256>>>(tmp, vrp, nullptr, nullptr, rectH, N_, HD_, N_, 0, 0, 0,
                            (long)N_*N_, (long)N_*HD_, (long)N_*HD_);

    // 6) rect projection + residual -> xx rows 1..196
    gemm_tf32<<<gx, 256>>>(rectH, Wr_proj, br_proj, x, xx, B_*N_, C_, C_, 0, 2, 0, 0,0,0);

    // 7) MLP
    ln_kernel<<<B_*T_, 128>>>(xx, hdn, g3, b3, B_*T_, B_*T_, 0, C_);
    dim3 gm1(24, 25), gm2(6, 25);
    gemm_tf32<<<gm1, 256>>>(hdn, W1, bm1, nullptr, h1, B_*T_, 4*C_, C_, 1, 0, 0, 0,0,0);
    gemm_tf32<<<gm2, 256>>>(h1, W2, bm2, xx, outp, B_*T_, C_, 4*C_, 0, 0, 0, 0,0,0);

    // 8) anchors pass-through
    int n4 = NC_*T_*C_/4;
    copy_kernel<<<(n4 + 255)/256, 256>>>(x + (long)16*T_*C_, outp + (long)16*T_*C_, n4);
}

// round 10
// speedup vs baseline: 2.1627x; 1.3638x over previous
#include <cuda_runtime.h>
#include <cuda_fp16.h>
#include <cstdint>

#define B_  16
#define NC_ 10
#define H_  6
#define C_  384
#define HD_ 64
#define T_  197
#define N_  196
#define BH_ (B_*H_)
#define CH_ (NC_*H_)
#define SCALE_ 0.125f
#define KP_ 224          // padded K for tmp/vrT (multiple of 32)

// weight-transpose buffer offsets (halves); layout [n][k] fp16
#define OW_QK  0
#define OW_QK2 147456
#define OW_V   294912
#define OW_R   442368
#define OW_1   589824
#define OW_2   1179648
#define WT_TOT 1769472

__device__ float g_n1 [26*C_];
__device__ __align__(16) __half g_n2x[B_*N_*C_];
__device__ __align__(16) __half g_n2a[NC_*N_*C_];
__device__ float g_qv [NC_*2*C_];
__device__ float g_k  [B_*C_];
__device__ float g_attn[B_*CH_];
__device__ float g_ctx[B_*C_];
__device__ __align__(16) __half g_qh_h[BH_*N_*HD_];
__device__ __align__(16) __half g_q2_h[BH_*N_*HD_];
__device__ __align__(16) __half g_kh_h[CH_*N_*HD_];
__device__ __align__(16) __half g_k2_h[CH_*N_*HD_];
__device__ __align__(16) __half g_vrT[BH_*HD_*KP_];
__device__ __align__(16) __half g_tmp[BH_*N_*KP_];
__device__ __align__(16) __half g_rectH[B_*N_*C_];   // flat [bh][n][d] == reshape(B,N,C)
__device__ float g_xx [B_*T_*C_];
__device__ __align__(16) __half g_hdn[B_*T_*C_];
__device__ __align__(16) __half g_h1 [B_*T_*4*C_];
__device__ __align__(16) __half g_wt [WT_TOT];

#define U32(x) __float_as_uint(x)

// fp16 mma m16n8k16 (fp32 accumulate)
__device__ __forceinline__ void mma16h(float* c, uint32_t a0, uint32_t a1, uint32_t a2, uint32_t a3,
                                       uint32_t b0, uint32_t b1)
{
    asm volatile("mma.sync.aligned.m16n8k16.row.col.f32.f16.f16.f32 "
                 "{%0,%1,%2,%3},{%4,%5,%6,%7},{%8,%9},{%0,%1,%2,%3};\n"
                 : "+f"(c[0]), "+f"(c[1]), "+f"(c[2]), "+f"(c[3])
                 : "r"(a0), "r"(a1), "r"(a2), "r"(a3), "r"(b0), "r"(b1));
}

__device__ __forceinline__ uint32_t pack_hf2(float lo, float hi) {
    uint32_t d;
    asm("cvt.rn.f16x2.f32 %0, %1, %2;" : "=r"(d) : "f"(hi), "f"(lo));
    return d;
}

__device__ __forceinline__ void cp16(uint32_t dst, const void* src, bool p) {
    int sz = p ? 16 : 0;
    asm volatile("cp.async.cg.shared.global [%0], [%1], 16, %2;" :: "r"(dst), "l"(src), "r"(sz));
}

__device__ __forceinline__ float gelu_f(float x) {
    return 0.5f * x * (1.f + erff(x * 0.7071067811865475f));
}

// ---------------- weight transpose-convert: W[K][N] fp32 -> Wt[N][K] fp16 ----------
__global__ void transpose_h(const float* __restrict__ src, __half* __restrict__ dst,
                            int K, int N)
{
    __shared__ float tile[32][33];
    int kb = blockIdx.y * 32, nb = blockIdx.x * 32;
    int tx = threadIdx.x, ty = threadIdx.y; // 32 x 8
#pragma unroll
    for (int i = 0; i < 32; i += 8)
        tile[ty + i][tx] = src[(size_t)(kb + ty + i) * N + nb + tx];
    __syncthreads();
#pragma unroll
    for (int i = 0; i < 32; i += 8)
        dst[(size_t)(nb + ty + i) * K + kb + tx] = __float2half(tile[tx][ty + i]);
}

// ---------------- zero pads of tmp (rows bh*196) and vrT (rows bh*64) ----------
__global__ void zero_pads(__half* __restrict__ tmp, __half* __restrict__ vrT)
{
    int row = blockIdx.x;
    int t = threadIdx.x;
    if (t >= KP_ - N_) return;
    if (row < BH_*N_) tmp[(size_t)row*KP_ + N_ + t] = __float2half(0.f);
    else {
        int r2 = row - BH_*N_;
        vrT[(size_t)r2*KP_ + N_ + t] = __float2half(0.f);
    }
}

// ---------------- LayerNorm (fp32 or fp16 output) ----------------
__global__ void ln_kernel(const float* __restrict__ in, void* __restrict__ outv,
                          const float* __restrict__ g, const float* __restrict__ bt,
                          int rows, int inner, long outer_stride, long inner_stride, int h16)
{
    int row = blockIdx.x;
    if (row >= rows) return;
    const float* src = in + (long)(row / inner) * outer_stride + (long)(row % inner) * inner_stride;
    int t = threadIdx.x;
    float v[3]; float s = 0.f;
#pragma unroll
    for (int i = 0; i < 3; i++) { v[i] = src[t + i*128]; s += v[i]; }
    __shared__ float red[4];
#pragma unroll
    for (int o = 16; o > 0; o >>= 1) s += __shfl_xor_sync(0xffffffffu, s, o);
    if ((t & 31) == 0) red[t >> 5] = s;
    __syncthreads();
    float mean = (red[0] + red[1] + red[2] + red[3]) * (1.f/384.f);
    float q = 0.f;
#pragma unroll
    for (int i = 0; i < 3; i++) { float d = v[i] - mean; q += d*d; }
#pragma unroll
    for (int o = 16; o > 0; o >>= 1) q += __shfl_xor_sync(0xffffffffu, q, o);
    __syncthreads();
    if ((t & 31) == 0) red[t >> 5] = q;
    __syncthreads();
    float var = (red[0] + red[1] + red[2] + red[3]) * (1.f/384.f);
    float rs = rsqrtf(var + 1e-5f);
#pragma unroll
    for (int i = 0; i < 3; i++) {
        int c = t + i*128;
        float o = (v[i] - mean) * rs * g[c] + bt[c];
        if (h16) ((__half*)outv)[(long)row*C_ + c] = __float2half(o);
        else     ((float*)outv)[(long)row*C_ + c] = o;
    }
}

// ---------------- small-M row GEMM (cls path), K=384, 4-way K-split ----------------
__global__ __launch_bounds__(256)
void rowgemm(const float* __restrict__ A, const float* __restrict__ W,
             const float* __restrict__ bias, float* __restrict__ out,
             int N, long out_stride)
{
    __shared__ float a_s[384];
    __shared__ float part[256];
    int row = blockIdx.x, cb = blockIdx.y * 64;
    int t = threadIdx.x;
    for (int i = t; i < 384; i += 256) a_s[i] = A[(size_t)row*384 + i];
    __syncthreads();
    int col = t & 63, sp = t >> 6;
    int base = sp * 96;
    float s0 = 0.f, s1 = 0.f;
    const float* Wp = W + (size_t)base*N + cb + col;
#pragma unroll 8
    for (int k = 0; k < 96; k += 2) {
        s0 += a_s[base+k]   * Wp[(size_t)(k)*N];
        s1 += a_s[base+k+1] * Wp[(size_t)(k+1)*N];
    }
    part[t] = s0 + s1;
    __syncthreads();
    if (t < 64) {
        float v = part[t] + part[64+t] + part[128+t] + part[192+t];
        if (bias) v += bias[cb + t];
        out[(size_t)row*out_stride + cb + t] = v;
    }
}

// ---------------- cls attention ----------------
__global__ void attn_cls_kernel(const float* __restrict__ qv, const float* __restrict__ k,
                                float* __restrict__ attn, float* __restrict__ ctx)
{
    int b = blockIdx.x, t = threadIdx.x;
    __shared__ float sl[CH_];
    if (t < CH_) {
        int n = t / H_, h = t % H_;
        float s = 0.f;
        for (int d = 0; d < HD_; d++) s += qv[n*2*C_ + h*HD_ + d] * k[b*C_ + h*HD_ + d];
        sl[t] = s * SCALE_;
    }
    __syncthreads();
    if (t < H_) {
        float mx = -1e30f;
        for (int n = 0; n < NC_; n++) mx = fmaxf(mx, sl[n*H_ + t]);
        float sum = 0.f;
        for (int n = 0; n < NC_; n++) { float e = expf(sl[n*H_ + t] - mx); sl[n*H_ + t] = e; sum += e; }
        float inv = 1.f / sum;
        for (int n = 0; n < NC_; n++) { sl[n*H_ + t] *= inv; attn[b*CH_ + n*H_ + t] = sl[n*H_ + t]; }
    }
    __syncthreads();
    {
        int h = t >> 6, d = t & 63;
        float s = 0.f;
        for (int n = 0; n < NC_; n++) s += sl[n*H_ + h] * qv[n*2*C_ + C_ + h*HD_ + d];
        ctx[b*C_ + t] = s;
    }
}

// ---------------- all-fp16 GEMM: out = act(A @ Bt^T + bias) (+res) ----------------
// modes: 0 row-major; 1 head-major fp16; 2 xx-rows fp32+res; 4 vrT fp16; 5 rectH flat [bh][n][d]
__global__ __launch_bounds__(256)
void gemm_h(const __half* __restrict__ A, const __half* __restrict__ Bt,
            const float* __restrict__ bias, const float* __restrict__ res,
            float* __restrict__ outF, __half* __restrict__ outH,
            int M, int N, int K, int lda, int ldb, int act, int mode,
            long zA, long zB)
{
    __shared__ __align__(16) __half As[128*40];
    __shared__ __align__(16) __half Bs[64*40];
    A  += (size_t)blockIdx.z * zA;
    Bt += (size_t)blockIdx.z * zB;

    int tid = threadIdx.x;
    int lane = tid & 31, warp = tid >> 5;
    int gid = lane >> 2, tig = lane & 3;
    int wm = warp >> 1, wn = warp & 1;
    int m0 = blockIdx.y * 128, n0 = blockIdx.x * 64;

    int ar = tid >> 1, ac = (tid & 1) * 16;
    int br = tid >> 2, bc = (tid & 3) * 8;

    float acc[2][4][4];
#pragma unroll
    for (int t = 0; t < 2; t++)
#pragma unroll
        for (int u = 0; u < 4; u++)
#pragma unroll
            for (int e = 0; e < 4; e++) acc[t][u][e] = 0.f;

    for (int kk = 0; kk < K; kk += 32) {
        __syncthreads();
        {
            float4 v0 = make_float4(0.f,0.f,0.f,0.f), v1 = v0;
            if (m0 + ar < M) {
                const __half* src = A + (size_t)(m0 + ar) * lda + kk + ac;
                v0 = *(const float4*)src;
                v1 = *(const float4*)(src + 8);
            }
            *(float4*)(As + ar*40 + ac)     = v0;
            *(float4*)(As + ar*40 + ac + 8) = v1;
        }
        {
            float4 v = *(const float4*)(Bt + (size_t)(n0 + br) * ldb + kk + bc);
            *(float4*)(Bs + br*40 + bc) = v;
        }
        __syncthreads();
#pragma unroll
        for (int ks = 0; ks < 2; ks++) {
            int ko = ks * 16;
            uint32_t a[2][4];
#pragma unroll
            for (int t = 0; t < 2; t++) {
                int mb = wm*32 + t*16;
                a[t][0] = *(const uint32_t*)(As + (mb+gid)*40   + ko + 2*tig);
                a[t][1] = *(const uint32_t*)(As + (mb+gid+8)*40 + ko + 2*tig);
                a[t][2] = *(const uint32_t*)(As + (mb+gid)*40   + ko + 2*tig + 8);
                a[t][3] = *(const uint32_t*)(As + (mb+gid+8)*40 + ko + 2*tig + 8);
            }
#pragma unroll
            for (int u = 0; u < 4; u++) {
                int cb = wn*32 + u*8;
                uint32_t b0 = *(const uint32_t*)(Bs + (cb+gid)*40 + ko + 2*tig);
                uint32_t b1 = *(const uint32_t*)(Bs + (cb+gid)*40 + ko + 2*tig + 8);
                mma16h(acc[0][u], a[0][0],a[0][1],a[0][2],a[0][3], b0,b1);
                mma16h(acc[1][u], a[1][0],a[1][1],a[1][2],a[1][3], b0,b1);
            }
        }
    }

    int bz = blockIdx.z;
#pragma unroll
    for (int t = 0; t < 2; t++) {
#pragma unroll
        for (int u = 0; u < 4; u++) {
            int rb = m0 + wm*32 + t*16 + gid;
            int cb = n0 + wn*32 + u*8 + 2*tig;
#pragma unroll
            for (int e = 0; e < 4; e++) {
                int r = rb + (e >> 1) * 8;
                int c = cb + (e & 1);
                if (r >= M) continue;
                float v = acc[t][u][e];
                if (bias) v += bias[c];
                if (act) v = gelu_f(v);
                size_t idx;
                if (mode == 0) idx = (size_t)r * N + c;
                else if (mode == 1) {
                    int bq = r / N_, n = r % N_;
                    idx = ((size_t)(bq*H_ + (c >> 6)) * N_ + n) * HD_ + (c & 63);
                } else if (mode == 2) {
                    int bq = r / N_, n = r % N_;
                    idx = ((size_t)bq*T_ + 1 + n) * C_ + c;
                } else if (mode == 4) {
                    int bq = r / N_, n = r % N_;
                    idx = ((size_t)(bq*H_ + (c >> 6)) * HD_ + (c & 63)) * KP_ + n;
                } else { // 5: rectH flat [bh][n][d]  (raw reshape semantics)
                    idx = ((size_t)bz * N_ + r) * HD_ + c;
                }
                if (outH) outH[idx] = __float2half(v);
                else {
                    if (res) v += res[idx];
                    outF[idx] = v;
                }
            }
        }
    }
}

// ---------------- fused rectified attention core (all-fp16 operands) ----------------
__global__ __launch_bounds__(256, 1)
void fused_attn3(const __half* __restrict__ qh, const __half* __restrict__ kh,
                 const __half* __restrict__ q2, const __half* __restrict__ k2,
                 const float* __restrict__ w2all, __half* __restrict__ tmp_out)
{
    __shared__ __align__(16) unsigned char smx[19712];
    __half* const stage = (__half*)smx;
    __half* const kbuf0 = (__half*)smx;
    __half* const kbuf1 = kbuf0 + 16*72;
    __half* const vbuf0 = kbuf1 + 16*72;
    __half* const vbuf1 = vbuf0 + 16*72;
    uint32_t* const L2_s  = (uint32_t*)(smx + 9216);
    uint32_t* const Rt2_s = (uint32_t*)(smx + 13568);

    int tid = threadIdx.x;
    int lane = tid & 31, warp = tid >> 5;
    int gid = lane >> 2, tig = lane & 3;
    int wm = warp >> 1, wn = warp & 1;

    int bh = blockIdx.z;
    int b = bh / H_, h = bh % H_;
    int n0 = blockIdx.y * 68;
    int p0 = blockIdx.x * 68;

    const __half* qh_b = qh + (size_t)bh * N_ * HD_;
    const __half* q2_b = q2 + (size_t)bh * N_ * HD_;

    uint32_t aq[4][4];
    for (int i = tid; i < 1024; i += 256) {
        int r = i >> 3, c8 = (i & 7) * 8;
        *(float4*)(stage + r*72 + c8) = *(const float4*)(qh_b + (size_t)(n0+r)*HD_ + c8);
    }
    __syncthreads();
    {
        int rb = warp * 16;
#pragma unroll
        for (int j = 0; j < 4; j++) {
            aq[j][0] = *(const uint32_t*)(stage + (rb+gid)*72   + 16*j + 2*tig);
            aq[j][1] = *(const uint32_t*)(stage + (rb+gid+8)*72 + 16*j + 2*tig);
            aq[j][2] = *(const uint32_t*)(stage + (rb+gid)*72   + 16*j + 2*tig + 8);
            aq[j][3] = *(const uint32_t*)(stage + (rb+gid+8)*72 + 16*j + 2*tig + 8);
        }
    }
    __syncthreads();
    uint32_t aq2[4][4];
    for (int i = tid; i < 1024; i += 256) {
        int r = i >> 3, c8 = (i & 7) * 8;
        *(float4*)(stage + r*72 + c8) = *(const float4*)(q2_b + (size_t)(p0+r)*HD_ + c8);
    }
    __syncthreads();
    {
        int pb = warp * 16;
#pragma unroll
        for (int j = 0; j < 4; j++) {
            aq2[j][0] = *(const uint32_t*)(stage + (pb+gid)*72   + 16*j + 2*tig);
            aq2[j][1] = *(const uint32_t*)(stage + (pb+gid+8)*72 + 16*j + 2*tig);
            aq2[j][2] = *(const uint32_t*)(stage + (pb+gid)*72   + 16*j + 2*tig + 8);
            aq2[j][3] = *(const uint32_t*)(stage + (pb+gid+8)*72 + 16*j + 2*tig + 8);
        }
    }
    __syncthreads();

    float acc[2][8][4];
#pragma unroll
    for (int t = 0; t < 2; t++)
#pragma unroll
        for (int u = 0; u < 8; u++)
#pragma unroll
            for (int e = 0; e < 4; e++) acc[t][u][e] = 0.f;

    uint32_t kd0 = (uint32_t)__cvta_generic_to_shared(kbuf0);
    uint32_t kd1 = (uint32_t)__cvta_generic_to_shared(kbuf1);
    uint32_t vd0 = (uint32_t)__cvta_generic_to_shared(vbuf0);
    uint32_t vd1 = (uint32_t)__cvta_generic_to_shared(vbuf1);

    int op  = tid >> 7;
    int pr  = (tid & 127) >> 3;
    int pc8 = (tid & 7) * 8;

    {
        const __half* src = (op ? k2 : kh) + (size_t)h * N_ * HD_ + (size_t)pr*HD_ + pc8;
        uint32_t d = (op ? vd0 : kd0) + (pr*72 + pc8)*2;
        cp16(d, src, true);
    }
    asm volatile("cp.async.commit_group;" ::: "memory");

    int buf = 0;
    for (int c = 0; c < NC_; c++) {
        float w2c = w2all[b*CH_ + h*NC_ + c];
        for (int mc = 0; mc < 13; mc++) {
            {
                int nc2 = c, nm = mc + 1;
                if (nm == 13) { nm = 0; nc2 = c + 1; }
                if (nc2 < NC_) {
                    int m = nm*16 + pr;
                    bool ok = m < N_;
                    const __half* basep = (op ? k2 : kh) + (size_t)(nc2*H_ + h) * N_ * HD_;
                    const __half* src = basep + (ok ? ((size_t)m*HD_ + pc8) : 0);
                    uint32_t d = (op ? (buf ? vd0 : vd1) : (buf ? kd0 : kd1)) + (pr*72 + pc8)*2;
                    cp16(d, src, ok);
                }
            }
            asm volatile("cp.async.commit_group;" ::: "memory");
            asm volatile("cp.async.wait_group 1;" ::: "memory");
            __syncthreads();

            const __half* KT  = buf ? kbuf1 : kbuf0;
            const __half* K2T = buf ? vbuf1 : vbuf0;

            float lacc[2][4];
#pragma unroll
            for (int t = 0; t < 2; t++)
#pragma unroll
                for (int e = 0; e < 4; e++) lacc[t][e] = 0.f;
#pragma unroll
            for (int j = 0; j < 4; j++) {
                uint32_t b0lo = *(const uint32_t*)(KT + gid*72     + 16*j + 2*tig);
                uint32_t b1lo = *(const uint32_t*)(KT + gid*72     + 16*j + 2*tig + 8);
                uint32_t b0hi = *(const uint32_t*)(KT + (gid+8)*72 + 16*j + 2*tig);
                uint32_t b1hi = *(const uint32_t*)(KT + (gid+8)*72 + 16*j + 2*tig + 8);
                mma16h(lacc[0], aq[j][0],aq[j][1],aq[j][2],aq[j][3], b0lo,b1lo);
                mma16h(lacc[1], aq[j][0],aq[j][1],aq[j][2],aq[j][3], b0hi,b1hi);
            }
            float racc[2][4];
#pragma unroll
            for (int t = 0; t < 2; t++)
#pragma unroll
                for (int e = 0; e < 4; e++) racc[t][e] = 0.f;
#pragma unroll
            for (int j = 0; j < 4; j++) {
                uint32_t b0lo = *(const uint32_t*)(K2T + gid*72     + 16*j + 2*tig);
                uint32_t b1lo = *(const uint32_t*)(K2T + gid*72     + 16*j + 2*tig + 8);
                uint32_t b0hi = *(const uint32_t*)(K2T + (gid+8)*72 + 16*j + 2*tig);
                uint32_t b1hi = *(const uint32_t*)(K2T + (gid+8)*72 + 16*j + 2*tig + 8);
                mma16h(racc[0], aq2[j][0],aq2[j][1],aq2[j][2],aq2[j][3], b0lo,b1lo);
                mma16h(racc[1], aq2[j][0],aq2[j][1],aq2[j][2],aq2[j][3], b0hi,b1hi);
            }
            {
                int nr = warp*16 + gid;
                int pb = warp*16;
#pragma unroll
                for (int t = 0; t < 2; t++) {
                    float l0 = w2c * fmaxf(0.f, -SCALE_*lacc[t][0]);
                    float l1 = w2c * fmaxf(0.f, -SCALE_*lacc[t][1]);
                    float l2 = w2c * fmaxf(0.f, -SCALE_*lacc[t][2]);
                    float l3 = w2c * fmaxf(0.f, -SCALE_*lacc[t][3]);
                    L2_s[(4*t+tig)*136 + nr]     = pack_hf2(l0, l1);
                    L2_s[(4*t+tig)*136 + nr + 8] = pack_hf2(l2, l3);
                    float r0 = fmaxf(0.f, SCALE_*racc[t][0]);
                    float r1 = fmaxf(0.f, SCALE_*racc[t][1]);
                    float r2 = fmaxf(0.f, SCALE_*racc[t][2]);
                    float r3 = fmaxf(0.f, SCALE_*racc[t][3]);
                    Rt2_s[(pb+gid)*12 + 4*t+tig]   = pack_hf2(r0, r1);
                    Rt2_s[(pb+gid+8)*12 + 4*t+tig] = pack_hf2(r2, r3);
                }
            }
            __syncthreads();
            {
                uint32_t a[2][4];
#pragma unroll
                for (int t = 0; t < 2; t++) {
                    int mb = wm*32 + t*16;
                    a[t][0] = L2_s[tig*136 + mb+gid];
                    a[t][1] = L2_s[tig*136 + mb+gid+8];
                    a[t][2] = L2_s[(tig+4)*136 + mb+gid];
                    a[t][3] = L2_s[(tig+4)*136 + mb+gid+8];
                }
#pragma unroll
                for (int u = 0; u < 8; u++) {
                    int cb = wn*64 + u*8;
                    uint32_t b0 = Rt2_s[(cb+gid)*12 + tig];
                    uint32_t b1 = Rt2_s[(cb+gid)*12 + tig+4];
                    mma16h(acc[0][u], a[0][0],a[0][1],a[0][2],a[0][3], b0,b1);
                    mma16h(acc[1][u], a[1][0],a[1][1],a[1][2],a[1][3], b0,b1);
                }
            }
            buf ^= 1;
        }
    }

    __half* o = tmp_out + (size_t)bh * N_ * KP_;
#pragma unroll
    for (int t = 0; t < 2; t++) {
#pragma unroll
        for (int u = 0; u < 8; u++) {
            int n = n0 + wm*32 + t*16 + gid;
            int p = p0 + wn*64 + u*8 + 2*tig;
            *(uint32_t*)(o + (size_t)n*KP_ + p)     = pack_hf2(acc[t][u][0], acc[t][u][1]);
            *(uint32_t*)(o + (size_t)(n+8)*KP_ + p) = pack_hf2(acc[t][u][2], acc[t][u][3]);
        }
    }
}

__global__ void copy_kernel(const float* __restrict__ src, float* __restrict__ dst, int n4)
{
    int i = blockIdx.x * blockDim.x + threadIdx.x;
    if (i < n4) ((float4*)dst)[i] = ((const float4*)src)[i];
}

extern "C" void kernel_launch(void* const* d_in, const int* in_sizes, int n_in,
                              void* d_out, int out_size)
{
    const float* x       = (const float*)d_in[0];
    const float* Wqv     = (const float*)d_in[1];
    const float* Wk      = (const float*)d_in[2];
    const float* Wq_proj = (const float*)d_in[3];
    const float* bq_proj = (const float*)d_in[4];
    const float* Wqk     = (const float*)d_in[5];
    const float* Wqk2    = (const float*)d_in[6];
    const float* Wv      = (const float*)d_in[7];
    const float* Wr_proj = (const float*)d_in[8];
    const float* br_proj = (const float*)d_in[9];
    const float* g1      = (const float*)d_in[10];
    const float* b1      = (const float*)d_in[11];
    const float* g2      = (const float*)d_in[12];
    const float* b2      = (const float*)d_in[13];
    const float* g3      = (const float*)d_in[14];
    const float* b3      = (const float*)d_in[15];
    const float* W1      = (const float*)d_in[16];
    const float* bm1     = (const float*)d_in[17];
    const float* W2      = (const float*)d_in[18];
    const float* bm2     = (const float*)d_in[19];
    float* outp = (float*)d_out;

    float *n1, *qv, *kb, *attn, *ctx, *xx;
    __half *n2x, *n2a, *qh, *q2, *kh, *k2, *vrT, *tmp, *rectH, *hdn, *h1, *wt;
    cudaGetSymbolAddress((void**)&n1, g_n1);
    cudaGetSymbolAddress((void**)&n2x, g_n2x);
    cudaGetSymbolAddress((void**)&n2a, g_n2a);
    cudaGetSymbolAddress((void**)&qv, g_qv);
    cudaGetSymbolAddress((void**)&kb, g_k);
    cudaGetSymbolAddress((void**)&attn, g_attn);
    cudaGetSymbolAddress((void**)&ctx, g_ctx);
    cudaGetSymbolAddress((void**)&qh, g_qh_h);
    cudaGetSymbolAddress((void**)&q2, g_q2_h);
    cudaGetSymbolAddress((void**)&kh, g_kh_h);
    cudaGetSymbolAddress((void**)&k2, g_k2_h);
    cudaGetSymbolAddress((void**)&vrT, g_vrT);
    cudaGetSymbolAddress((void**)&tmp, g_tmp);
    cudaGetSymbolAddress((void**)&rectH, g_rectH);
    cudaGetSymbolAddress((void**)&xx, g_xx);
    cudaGetSymbolAddress((void**)&hdn, g_hdn);
    cudaGetSymbolAddress((void**)&h1, g_h1);
    cudaGetSymbolAddress((void**)&wt, g_wt);

    // 0) weight transpose-convert to fp16 [n][k]; zero K-pads of tmp/vrT
    dim3 tt(32, 8);
    transpose_h<<<dim3(12, 12), tt>>>(Wqk,     wt + OW_QK,  C_, C_);
    transpose_h<<<dim3(12, 12), tt>>>(Wqk2,    wt + OW_QK2, C_, C_);
    transpose_h<<<dim3(12, 12), tt>>>(Wv,      wt + OW_V,   C_, C_);
    transpose_h<<<dim3(12, 12), tt>>>(Wr_proj, wt + OW_R,   C_, C_);
    transpose_h<<<dim3(48, 12), tt>>>(W1,      wt + OW_1,   C_, 4*C_);
    transpose_h<<<dim3(12, 48), tt>>>(W2,      wt + OW_2,   4*C_, C_);
    zero_pads<<<BH_*N_ + BH_*HD_, 32>>>(tmp, vrT);

    // 1) LayerNorms
    ln_kernel<<<26, 128>>>(x, n1, g1, b1, 26, 26, 0, (long)T_*C_, 0);
    ln_kernel<<<B_*N_, 128>>>(x + C_, n2x, g2, b2, B_*N_, N_, (long)T_*C_, C_, 1);
    ln_kernel<<<NC_*N_, 128>>>(x + (long)16*T_*C_ + C_, n2a, g2, b2, NC_*N_, N_, (long)T_*C_, C_, 1);

    // 2) cls path (fp32)
    rowgemm<<<dim3(NC_, 12), 256>>>(n1 + 16*C_, Wqv, nullptr, qv, 2*C_, 2*C_);
    rowgemm<<<dim3(B_, 6), 256>>>(n1, Wk, nullptr, kb, C_, C_);
    attn_cls_kernel<<<B_, 384>>>(qv, kb, attn, ctx);
    rowgemm<<<dim3(B_, 6), 256>>>(ctx, Wq_proj, bq_proj, xx, C_, (long)T_*C_);

    // 3) head projections (fp16 GEMMs)
    dim3 gx(6, 25), ga(6, 16);
    gemm_h<<<gx, 256>>>(n2x, wt + OW_QK,  nullptr, nullptr, nullptr, qh,
                        B_*N_, C_, C_, C_, C_, 0, 1, 0, 0);
    gemm_h<<<gx, 256>>>(n2x, wt + OW_QK2, nullptr, nullptr, nullptr, q2,
                        B_*N_, C_, C_, C_, C_, 0, 1, 0, 0);
    gemm_h<<<gx, 256>>>(n2x, wt + OW_V,   nullptr, nullptr, nullptr, vrT,
                        B_*N_, C_, C_, C_, C_, 0, 4, 0, 0);
    gemm_h<<<ga, 256>>>(n2a, wt + OW_QK,  nullptr, nullptr, nullptr, kh,
                        NC_*N_, C_, C_, C_, C_, 0, 1, 0, 0);
    gemm_h<<<ga, 256>>>(n2a, wt + OW_QK2, nullptr, nullptr, nullptr, k2,
                        NC_*N_, C_, C_, C_, C_, 0, 1, 0, 0);

    // 4) fused rectified attention core -> tmp (fp16, K-padded)
    dim3 gf(2, 2, BH_);
    fused_attn3<<<gf, 256>>>(qh, kh, q2, k2, attn, tmp);

    // 5) rect = tmp @ vr (all-fp16, batched over bh) -> rectH flat [bh][n][d]
    gemm_h<<<dim3(1, 2, BH_), 256>>>(tmp, vrT, nullptr, nullptr, nullptr, rectH,
                                     N_, HD_, KP_, KP_, KP_, 0, 5,
                                     (long)N_*KP_, (long)HD_*KP_);

    // 6) rect projection + residual -> xx rows 1..196 (fp32); rectH is [B*N][C] row-major
    gemm_h<<<gx, 256>>>(rectH, wt + OW_R, br_proj, x, xx, nullptr,
                        B_*N_, C_, C_, C_, C_, 0, 2, 0, 0);

    // 7) MLP
    ln_kernel<<<B_*T_, 128>>>(xx, hdn, g3, b3, B_*T_, B_*T_, 0, C_, 1);
    gemm_h<<<dim3(24, 25), 256>>>(hdn, wt + OW_1, bm1, nullptr, nullptr, h1,
                                  B_*T_, 4*C_, C_, C_, C_, 1, 0, 0, 0);
    gemm_h<<<dim3(6, 25), 256>>>(h1, wt + OW_2, bm2, xx, outp, nullptr,
                                 B_*T_, C_, 4*C_, 4*C_, 4*C_, 0, 0, 0, 0);

    // 8) anchors pass-through
    int n4 = NC_*T_*C_/4;
    copy_kernel<<<(n4 + 255)/256, 256>>>(x + (long)16*T_*C_, outp + (long)16*T_*C_, n4);
}

// round 11
// speedup vs baseline: 2.3343x; 1.0793x over previous
#include <cuda_runtime.h>
#include <cuda_fp16.h>
#include <cstdint>

#define B_  16
#define NC_ 10
#define H_  6
#define C_  384
#define HD_ 64
#define T_  197
#define N_  196
#define BH_ (B_*H_)
#define CH_ (NC_*H_)
#define SCALE_ 0.125f
#define KP_ 224          // padded K for tmp/vrT (multiple of 32)

// weight-transpose buffer offsets (halves); layout [n][k] fp16
#define OW_QK  0
#define OW_QK2 147456
#define OW_V   294912
#define OW_R   442368
#define OW_1   589824
#define OW_2   1179648
#define WT_TOT 1769472

__device__ float g_n1 [26*C_];
__device__ __align__(16) __half g_n2x[B_*N_*C_];
__device__ __align__(16) __half g_n2a[NC_*N_*C_];
__device__ float g_qv [NC_*2*C_];
__device__ float g_k  [B_*C_];
__device__ float g_attn[B_*CH_];
__device__ float g_ctx[B_*C_];
__device__ __align__(16) __half g_qh_h[BH_*N_*HD_];
__device__ __align__(16) __half g_q2_h[BH_*N_*HD_];
__device__ __align__(16) __half g_kh_h[CH_*N_*HD_];
__device__ __align__(16) __half g_k2_h[CH_*N_*HD_];
__device__ __align__(16) __half g_vrT[BH_*HD_*KP_];
__device__ __align__(16) __half g_tmp[BH_*N_*KP_];
__device__ __align__(16) __half g_rectH[B_*N_*C_];   // flat [bh][n][d] == reshape(B,N,C)
__device__ float g_xx [B_*T_*C_];
__device__ __align__(16) __half g_hdn[B_*T_*C_];
__device__ __align__(16) __half g_h1 [B_*T_*4*C_];
__device__ __align__(16) __half g_wt [WT_TOT];

#define U32(x) __float_as_uint(x)

// fp16 mma m16n8k16 (fp32 accumulate)
__device__ __forceinline__ void mma16h(float* c, uint32_t a0, uint32_t a1, uint32_t a2, uint32_t a3,
                                       uint32_t b0, uint32_t b1)
{
    asm volatile("mma.sync.aligned.m16n8k16.row.col.f32.f16.f16.f32 "
                 "{%0,%1,%2,%3},{%4,%5,%6,%7},{%8,%9},{%0,%1,%2,%3};\n"
                 : "+f"(c[0]), "+f"(c[1]), "+f"(c[2]), "+f"(c[3])
                 : "r"(a0), "r"(a1), "r"(a2), "r"(a3), "r"(b0), "r"(b1));
}

__device__ __forceinline__ uint32_t pack_hf2(float lo, float hi) {
    uint32_t d;
    asm("cvt.rn.f16x2.f32 %0, %1, %2;" : "=r"(d) : "f"(hi), "f"(lo));
    return d;
}

__device__ __forceinline__ void cp16(uint32_t dst, const void* src, bool p) {
    int sz = p ? 16 : 0;
    asm volatile("cp.async.cg.shared.global [%0], [%1], 16, %2;" :: "r"(dst), "l"(src), "r"(sz));
}

__device__ __forceinline__ float gelu_f(float x) {
    return 0.5f * x * (1.f + erff(x * 0.7071067811865475f));
}

// ---------------- merged weight transpose-convert (one launch, 1728 tiles) --------
__global__ void transpose_all(const float* __restrict__ Wqk, const float* __restrict__ Wqk2,
                              const float* __restrict__ Wv,  const float* __restrict__ Wr,
                              const float* __restrict__ W1,  const float* __restrict__ W2,
                              __half* __restrict__ wt)
{
    __shared__ float tile[32][33];
    int bid = blockIdx.x;
    const float* src; __half* dst; int K, N, tn;
    if      (bid < 144)  { src = Wqk;  dst = wt + OW_QK;  K = C_;   N = C_;   tn = bid; }
    else if (bid < 288)  { src = Wqk2; dst = wt + OW_QK2; K = C_;   N = C_;   tn = bid - 144; }
    else if (bid < 432)  { src = Wv;   dst = wt + OW_V;   K = C_;   N = C_;   tn = bid - 288; }
    else if (bid < 576)  { src = Wr;   dst = wt + OW_R;   K = C_;   N = C_;   tn = bid - 432; }
    else if (bid < 1152) { src = W1;   dst = wt + OW_1;   K = C_;   N = 4*C_; tn = bid - 576; }
    else                 { src = W2;   dst = wt + OW_2;   K = 4*C_; N = C_;   tn = bid - 1152; }
    int ntx = N >> 5;
    int nb = (tn % ntx) * 32, kb = (tn / ntx) * 32;
    int tx = threadIdx.x, ty = threadIdx.y; // 32 x 8
#pragma unroll
    for (int i = 0; i < 32; i += 8)
        tile[ty + i][tx] = src[(size_t)(kb + ty + i) * N + nb + tx];
    __syncthreads();
#pragma unroll
    for (int i = 0; i < 32; i += 8)
        dst[(size_t)(nb + ty + i) * K + kb + tx] = __float2half(tile[tx][ty + i]);
}

// ---------------- zero pads of tmp (rows bh*196) and vrT (rows bh*64) ----------
__global__ void zero_pads(__half* __restrict__ tmp, __half* __restrict__ vrT)
{
    int row = blockIdx.x;
    int t = threadIdx.x;
    if (t >= KP_ - N_) return;
    if (row < BH_*N_) tmp[(size_t)row*KP_ + N_ + t] = __float2half(0.f);
    else {
        int r2 = row - BH_*N_;
        vrT[(size_t)r2*KP_ + N_ + t] = __float2half(0.f);
    }
}

// ---------------- LayerNorm (fp32 or fp16 output) ----------------
__global__ void ln_kernel(const float* __restrict__ in, void* __restrict__ outv,
                          const float* __restrict__ g, const float* __restrict__ bt,
                          int rows, int inner, long outer_stride, long inner_stride, int h16)
{
    int row = blockIdx.x;
    if (row >= rows) return;
    const float* src = in + (long)(row / inner) * outer_stride + (long)(row % inner) * inner_stride;
    int t = threadIdx.x;
    float v[3]; float s = 0.f;
#pragma unroll
    for (int i = 0; i < 3; i++) { v[i] = src[t + i*128]; s += v[i]; }
    __shared__ float red[4];
#pragma unroll
    for (int o = 16; o > 0; o >>= 1) s += __shfl_xor_sync(0xffffffffu, s, o);
    if ((t & 31) == 0) red[t >> 5] = s;
    __syncthreads();
    float mean = (red[0] + red[1] + red[2] + red[3]) * (1.f/384.f);
    float q = 0.f;
#pragma unroll
    for (int i = 0; i < 3; i++) { float d = v[i] - mean; q += d*d; }
#pragma unroll
    for (int o = 16; o > 0; o >>= 1) q += __shfl_xor_sync(0xffffffffu, q, o);
    __syncthreads();
    if ((t & 31) == 0) red[t >> 5] = q;
    __syncthreads();
    float var = (red[0] + red[1] + red[2] + red[3]) * (1.f/384.f);
    float rs = rsqrtf(var + 1e-5f);
#pragma unroll
    for (int i = 0; i < 3; i++) {
        int c = t + i*128;
        float o = (v[i] - mean) * rs * g[c] + bt[c];
        if (h16) ((__half*)outv)[(long)row*C_ + c] = __float2half(o);
        else     ((float*)outv)[(long)row*C_ + c] = o;
    }
}

// ---------------- small-M row GEMM (cls path), K=384, 4-way K-split ----------------
__global__ __launch_bounds__(256)
void rowgemm(const float* __restrict__ A, const float* __restrict__ W,
             const float* __restrict__ bias, float* __restrict__ out,
             int N, long out_stride)
{
    __shared__ float a_s[384];
    __shared__ float part[256];
    int row = blockIdx.x, cb = blockIdx.y * 64;
    int t = threadIdx.x;
    for (int i = t; i < 384; i += 256) a_s[i] = A[(size_t)row*384 + i];
    __syncthreads();
    int col = t & 63, sp = t >> 6;
    int base = sp * 96;
    float s0 = 0.f, s1 = 0.f;
    const float* Wp = W + (size_t)base*N + cb + col;
#pragma unroll 8
    for (int k = 0; k < 96; k += 2) {
        s0 += a_s[base+k]   * Wp[(size_t)(k)*N];
        s1 += a_s[base+k+1] * Wp[(size_t)(k+1)*N];
    }
    part[t] = s0 + s1;
    __syncthreads();
    if (t < 64) {
        float v = part[t] + part[64+t] + part[128+t] + part[192+t];
        if (bias) v += bias[cb + t];
        out[(size_t)row*out_stride + cb + t] = v;
    }
}

// ---------------- cls attention ----------------
__global__ void attn_cls_kernel(const float* __restrict__ qv, const float* __restrict__ k,
                                float* __restrict__ attn, float* __restrict__ ctx)
{
    int b = blockIdx.x, t = threadIdx.x;
    __shared__ float sl[CH_];
    if (t < CH_) {
        int n = t / H_, h = t % H_;
        float s = 0.f;
        for (int d = 0; d < HD_; d++) s += qv[n*2*C_ + h*HD_ + d] * k[b*C_ + h*HD_ + d];
        sl[t] = s * SCALE_;
    }
    __syncthreads();
    if (t < H_) {
        float mx = -1e30f;
        for (int n = 0; n < NC_; n++) mx = fmaxf(mx, sl[n*H_ + t]);
        float sum = 0.f;
        for (int n = 0; n < NC_; n++) { float e = expf(sl[n*H_ + t] - mx); sl[n*H_ + t] = e; sum += e; }
        float inv = 1.f / sum;
        for (int n = 0; n < NC_; n++) { sl[n*H_ + t] *= inv; attn[b*CH_ + n*H_ + t] = sl[n*H_ + t]; }
    }
    __syncthreads();
    {
        int h = t >> 6, d = t & 63;
        float s = 0.f;
        for (int n = 0; n < NC_; n++) s += sl[n*H_ + h] * qv[n*2*C_ + C_ + h*HD_ + d];
        ctx[b*C_ + t] = s;
    }
}

// ---------------- all-fp16 GEMM, 2-stage cp.async pipeline ----------------
// modes: 0 row-major; 1 head-major fp16; 2 xx-rows fp32+res; 4 vrT fp16; 5 rectH flat [bh][n][d]
// Requires: K % 32 == 0, N % 64 == 0 (all call sites satisfy this).
__global__ __launch_bounds__(256)
void gemm_h(const __half* __restrict__ A, const __half* __restrict__ Bt,
            const float* __restrict__ bias, const float* __restrict__ res,
            float* __restrict__ outF, __half* __restrict__ outH,
            int M, int N, int K, int lda, int ldb, int act, int mode,
            long zA, long zB)
{
    __shared__ __align__(16) __half As[2][128*40];
    __shared__ __align__(16) __half Bs[2][64*40];
    A  += (size_t)blockIdx.z * zA;
    Bt += (size_t)blockIdx.z * zB;

    int tid = threadIdx.x;
    int lane = tid & 31, warp = tid >> 5;
    int gid = lane >> 2, tig = lane & 3;
    int wm = warp >> 1, wn = warp & 1;
    int m0 = blockIdx.y * 128, n0 = blockIdx.x * 64;

    int ar = tid >> 1, ac = (tid & 1) * 16;   // A: 16 halves (2 chunks) per thread
    int br = tid >> 2, bc = (tid & 3) * 8;    // B: 8 halves (1 chunk) per thread

    uint32_t aB[2], bB[2];
#pragma unroll
    for (int s = 0; s < 2; s++) {
        aB[s] = (uint32_t)__cvta_generic_to_shared(&As[s][0]);
        bB[s] = (uint32_t)__cvta_generic_to_shared(&Bs[s][0]);
    }

    bool okA = (m0 + ar < M);
    int nk = K >> 5;

#define GISSUE(it_, st_) do { \
    int kk = (it_) * 32; \
    const __half* sa = A + (size_t)(m0 + ar) * lda + kk + ac; \
    cp16(aB[st_] + (ar*40 + ac)*2,      okA ? sa : (const __half*)A,       okA); \
    cp16(aB[st_] + (ar*40 + ac)*2 + 16, okA ? (sa + 8) : (const __half*)A, okA); \
    cp16(bB[st_] + (br*40 + bc)*2, Bt + (size_t)(n0 + br) * ldb + kk + bc, true); \
    asm volatile("cp.async.commit_group;" ::: "memory"); \
} while (0)

    float acc[2][4][4];
#pragma unroll
    for (int t = 0; t < 2; t++)
#pragma unroll
        for (int u = 0; u < 4; u++)
#pragma unroll
            for (int e = 0; e < 4; e++) acc[t][u][e] = 0.f;

    GISSUE(0, 0);

    for (int it = 0; it < nk; it++) {
        asm volatile("cp.async.wait_group 0;" ::: "memory");
        __syncthreads();
        int st = it & 1;
        if (it + 1 < nk) GISSUE(it + 1, st ^ 1);
        const __half* Af = As[st];
        const __half* Bf = Bs[st];
#pragma unroll
        for (int ks = 0; ks < 2; ks++) {
            int ko = ks * 16;
            uint32_t a[2][4];
#pragma unroll
            for (int t = 0; t < 2; t++) {
                int mb = wm*32 + t*16;
                a[t][0] = *(const uint32_t*)(Af + (mb+gid)*40   + ko + 2*tig);
                a[t][1] = *(const uint32_t*)(Af + (mb+gid+8)*40 + ko + 2*tig);
                a[t][2] = *(const uint32_t*)(Af + (mb+gid)*40   + ko + 2*tig + 8);
                a[t][3] = *(const uint32_t*)(Af + (mb+gid+8)*40 + ko + 2*tig + 8);
            }
#pragma unroll
            for (int u = 0; u < 4; u++) {
                int cb = wn*32 + u*8;
                uint32_t b0 = *(const uint32_t*)(Bf + (cb+gid)*40 + ko + 2*tig);
                uint32_t b1 = *(const uint32_t*)(Bf + (cb+gid)*40 + ko + 2*tig + 8);
                mma16h(acc[0][u], a[0][0],a[0][1],a[0][2],a[0][3], b0,b1);
                mma16h(acc[1][u], a[1][0],a[1][1],a[1][2],a[1][3], b0,b1);
            }
        }
    }
#undef GISSUE

    int bz = blockIdx.z;
#pragma unroll
    for (int t = 0; t < 2; t++) {
#pragma unroll
        for (int u = 0; u < 4; u++) {
            int rb = m0 + wm*32 + t*16 + gid;
            int cb = n0 + wn*32 + u*8 + 2*tig;
#pragma unroll
            for (int e = 0; e < 4; e++) {
                int r = rb + (e >> 1) * 8;
                int c = cb + (e & 1);
                if (r >= M) continue;
                float v = acc[t][u][e];
                if (bias) v += bias[c];
                if (act) v = gelu_f(v);
                size_t idx;
                if (mode == 0) idx = (size_t)r * N + c;
                else if (mode == 1) {
                    int bq = r / N_, n = r % N_;
                    idx = ((size_t)(bq*H_ + (c >> 6)) * N_ + n) * HD_ + (c & 63);
                } else if (mode == 2) {
                    int bq = r / N_, n = r % N_;
                    idx = ((size_t)bq*T_ + 1 + n) * C_ + c;
                } else if (mode == 4) {
                    int bq = r / N_, n = r % N_;
                    idx = ((size_t)(bq*H_ + (c >> 6)) * HD_ + (c & 63)) * KP_ + n;
                } else { // 5: rectH flat [bh][n][d]
                    idx = ((size_t)bz * N_ + r) * HD_ + c;
                }
                if (outH) outH[idx] = __float2half(v);
                else {
                    if (res) v += res[idx];
                    outF[idx] = v;
                }
            }
        }
    }
}

// ---------------- fused rectified attention core (all-fp16 operands) ----------------
__global__ __launch_bounds__(256, 1)
void fused_attn3(const __half* __restrict__ qh, const __half* __restrict__ kh,
                 const __half* __restrict__ q2, const __half* __restrict__ k2,
                 const float* __restrict__ w2all, __half* __restrict__ tmp_out)
{
    __shared__ __align__(16) unsigned char smx[19712];
    __half* const stage = (__half*)smx;
    __half* const kbuf0 = (__half*)smx;
    __half* const kbuf1 = kbuf0 + 16*72;
    __half* const vbuf0 = kbuf1 + 16*72;
    __half* const vbuf1 = vbuf0 + 16*72;
    uint32_t* const L2_s  = (uint32_t*)(smx + 9216);
    uint32_t* const Rt2_s = (uint32_t*)(smx + 13568);

    int tid = threadIdx.x;
    int lane = tid & 31, warp = tid >> 5;
    int gid = lane >> 2, tig = lane & 3;
    int wm = warp >> 1, wn = warp & 1;

    int bh = blockIdx.z;
    int b = bh / H_, h = bh % H_;
    int n0 = blockIdx.y * 68;
    int p0 = blockIdx.x * 68;

    const __half* qh_b = qh + (size_t)bh * N_ * HD_;
    const __half* q2_b = q2 + (size_t)bh * N_ * HD_;

    uint32_t aq[4][4];
    for (int i = tid; i < 1024; i += 256) {
        int r = i >> 3, c8 = (i & 7) * 8;
        *(float4*)(stage + r*72 + c8) = *(const float4*)(qh_b + (size_t)(n0+r)*HD_ + c8);
    }
    __syncthreads();
    {
        int rb = warp * 16;
#pragma unroll
        for (int j = 0; j < 4; j++) {
            aq[j][0] = *(const uint32_t*)(stage + (rb+gid)*72   + 16*j + 2*tig);
            aq[j][1] = *(const uint32_t*)(stage + (rb+gid+8)*72 + 16*j + 2*tig);
            aq[j][2] = *(const uint32_t*)(stage + (rb+gid)*72   + 16*j + 2*tig + 8);
            aq[j][3] = *(const uint32_t*)(stage + (rb+gid+8)*72 + 16*j + 2*tig + 8);
        }
    }
    __syncthreads();
    uint32_t aq2[4][4];
    for (int i = tid; i < 1024; i += 256) {
        int r = i >> 3, c8 = (i & 7) * 8;
        *(float4*)(stage + r*72 + c8) = *(const float4*)(q2_b + (size_t)(p0+r)*HD_ + c8);
    }
    __syncthreads();
    {
        int pb = warp * 16;
#pragma unroll
        for (int j = 0; j < 4; j++) {
            aq2[j][0] = *(const uint32_t*)(stage + (pb+gid)*72   + 16*j + 2*tig);
            aq2[j][1] = *(const uint32_t*)(stage + (pb+gid+8)*72 + 16*j + 2*tig);
            aq2[j][2] = *(const uint32_t*)(stage + (pb+gid)*72   + 16*j + 2*tig + 8);
            aq2[j][3] = *(const uint32_t*)(stage + (pb+gid+8)*72 + 16*j + 2*tig + 8);
        }
    }
    __syncthreads();

    float acc[2][8][4];
#pragma unroll
    for (int t = 0; t < 2; t++)
#pragma unroll
        for (int u = 0; u < 8; u++)
#pragma unroll
            for (int e = 0; e < 4; e++) acc[t][u][e] = 0.f;

    uint32_t kd0 = (uint32_t)__cvta_generic_to_shared(kbuf0);
    uint32_t kd1 = (uint32_t)__cvta_generic_to_shared(kbuf1);
    uint32_t vd0 = (uint32_t)__cvta_generic_to_shared(vbuf0);
    uint32_t vd1 = (uint32_t)__cvta_generic_to_shared(vbuf1);

    int op  = tid >> 7;
    int pr  = (tid & 127) >> 3;
    int pc8 = (tid & 7) * 8;

    {
        const __half* src = (op ? k2 : kh) + (size_t)h * N_ * HD_ + (size_t)pr*HD_ + pc8;
        uint32_t d = (op ? vd0 : kd0) + (pr*72 + pc8)*2;
        cp16(d, src, true);
    }
    asm volatile("cp.async.commit_group;" ::: "memory");

    int buf = 0;
    for (int c = 0; c < NC_; c++) {
        float w2c = w2all[b*CH_ + h*NC_ + c];
        for (int mc = 0; mc < 13; mc++) {
            {
                int nc2 = c, nm = mc + 1;
                if (nm == 13) { nm = 0; nc2 = c + 1; }
                if (nc2 < NC_) {
                    int m = nm*16 + pr;
                    bool ok = m < N_;
                    const __half* basep = (op ? k2 : kh) + (size_t)(nc2*H_ + h) * N_ * HD_;
                    const __half* src = basep + (ok ? ((size_t)m*HD_ + pc8) : 0);
                    uint32_t d = (op ? (buf ? vd0 : vd1) : (buf ? kd0 : kd1)) + (pr*72 + pc8)*2;
                    cp16(d, src, ok);
                }
            }
            asm volatile("cp.async.commit_group;" ::: "memory");
            asm volatile("cp.async.wait_group 1;" ::: "memory");
            __syncthreads();

            const __half* KT  = buf ? kbuf1 : kbuf0;
            const __half* K2T = buf ? vbuf1 : vbuf0;

            float lacc[2][4];
#pragma unroll
            for (int t = 0; t < 2; t++)
#pragma unroll
                for (int e = 0; e < 4; e++) lacc[t][e] = 0.f;
#pragma unroll
            for (int j = 0; j < 4; j++) {
                uint32_t b0lo = *(const uint32_t*)(KT + gid*72     + 16*j + 2*tig);
                uint32_t b1lo = *(const uint32_t*)(KT + gid*72     + 16*j + 2*tig + 8);
                uint32_t b0hi = *(const uint32_t*)(KT + (gid+8)*72 + 16*j + 2*tig);
                uint32_t b1hi = *(const uint32_t*)(KT + (gid+8)*72 + 16*j + 2*tig + 8);
                mma16h(lacc[0], aq[j][0],aq[j][1],aq[j][2],aq[j][3], b0lo,b1lo);
                mma16h(lacc[1], aq[j][0],aq[j][1],aq[j][2],aq[j][3], b0hi,b1hi);
            }
            float racc[2][4];
#pragma unroll
            for (int t = 0; t < 2; t++)
#pragma unroll
                for (int e = 0; e < 4; e++) racc[t][e] = 0.f;
#pragma unroll
            for (int j = 0; j < 4; j++) {
                uint32_t b0lo = *(const uint32_t*)(K2T + gid*72     + 16*j + 2*tig);
                uint32_t b1lo = *(const uint32_t*)(K2T + gid*72     + 16*j + 2*tig + 8);
                uint32_t b0hi = *(const uint32_t*)(K2T + (gid+8)*72 + 16*j + 2*tig);
                uint32_t b1hi = *(const uint32_t*)(K2T + (gid+8)*72 + 16*j + 2*tig + 8);
                mma16h(racc[0], aq2[j][0],aq2[j][1],aq2[j][2],aq2[j][3], b0lo,b1lo);
                mma16h(racc[1], aq2[j][0],aq2[j][1],aq2[j][2],aq2[j][3], b0hi,b1hi);
            }
            {
                int nr = warp*16 + gid;
                int pb = warp*16;
#pragma unroll
                for (int t = 0; t < 2; t++) {
                    float l0 = w2c * fmaxf(0.f, -SCALE_*lacc[t][0]);
                    float l1 = w2c * fmaxf(0.f, -SCALE_*lacc[t][1]);
                    float l2 = w2c * fmaxf(0.f, -SCALE_*lacc[t][2]);
                    float l3 = w2c * fmaxf(0.f, -SCALE_*lacc[t][3]);
                    L2_s[(4*t+tig)*136 + nr]     = pack_hf2(l0, l1);
                    L2_s[(4*t+tig)*136 + nr + 8] = pack_hf2(l2, l3);
                    float r0 = fmaxf(0.f, SCALE_*racc[t][0]);
                    float r1 = fmaxf(0.f, SCALE_*racc[t][1]);
                    float r2 = fmaxf(0.f, SCALE_*racc[t][2]);
                    float r3 = fmaxf(0.f, SCALE_*racc[t][3]);
                    Rt2_s[(pb+gid)*12 + 4*t+tig]   = pack_hf2(r0, r1);
                    Rt2_s[(pb+gid+8)*12 + 4*t+tig] = pack_hf2(r2, r3);
                }
            }
            __syncthreads();
            {
                uint32_t a[2][4];
#pragma unroll
                for (int t = 0; t < 2; t++) {
                    int mb = wm*32 + t*16;
                    a[t][0] = L2_s[tig*136 + mb+gid];
                    a[t][1] = L2_s[tig*136 + mb+gid+8];
                    a[t][2] = L2_s[(tig+4)*136 + mb+gid];
                    a[t][3] = L2_s[(tig+4)*136 + mb+gid+8];
                }
#pragma unroll
                for (int u = 0; u < 8; u++) {
                    int cb = wn*64 + u*8;
                    uint32_t b0 = Rt2_s[(cb+gid)*12 + tig];
                    uint32_t b1 = Rt2_s[(cb+gid)*12 + tig+4];
                    mma16h(acc[0][u], a[0][0],a[0][1],a[0][2],a[0][3], b0,b1);
                    mma16h(acc[1][u], a[1][0],a[1][1],a[1][2],a[1][3], b0,b1);
                }
            }
            buf ^= 1;
        }
    }

    __half* o = tmp_out + (size_t)bh * N_ * KP_;
#pragma unroll
    for (int t = 0; t < 2; t++) {
#pragma unroll
        for (int u = 0; u < 8; u++) {
            int n = n0 + wm*32 + t*16 + gid;
            int p = p0 + wn*64 + u*8 + 2*tig;
            *(uint32_t*)(o + (size_t)n*KP_ + p)     = pack_hf2(acc[t][u][0], acc[t][u][1]);
            *(uint32_t*)(o + (size_t)(n+8)*KP_ + p) = pack_hf2(acc[t][u][2], acc[t][u][3]);
        }
    }
}

__global__ void copy_kernel(const float* __restrict__ src, float* __restrict__ dst, int n4)
{
    int i = blockIdx.x * blockDim.x + threadIdx.x;
    if (i < n4) ((float4*)dst)[i] = ((const float4*)src)[i];
}

extern "C" void kernel_launch(void* const* d_in, const int* in_sizes, int n_in,
                              void* d_out, int out_size)
{
    const float* x       = (const float*)d_in[0];
    const float* Wqv     = (const float*)d_in[1];
    const float* Wk      = (const float*)d_in[2];
    const float* Wq_proj = (const float*)d_in[3];
    const float* bq_proj = (const float*)d_in[4];
    const float* Wqk     = (const float*)d_in[5];
    const float* Wqk2    = (const float*)d_in[6];
    const float* Wv      = (const float*)d_in[7];
    const float* Wr_proj = (const float*)d_in[8];
    const float* br_proj = (const float*)d_in[9];
    const float* g1      = (const float*)d_in[10];
    const float* b1      = (const float*)d_in[11];
    const float* g2      = (const float*)d_in[12];
    const float* b2      = (const float*)d_in[13];
    const float* g3      = (const float*)d_in[14];
    const float* b3      = (const float*)d_in[15];
    const float* W1      = (const float*)d_in[16];
    const float* bm1     = (const float*)d_in[17];
    const float* W2      = (const float*)d_in[18];
    const float* bm2     = (const float*)d_in[19];
    float* outp = (float*)d_out;

    float *n1, *qv, *kb, *attn, *ctx, *xx;
    __half *n2x, *n2a, *qh, *q2, *kh, *k2, *vrT, *tmp, *rectH, *hdn, *h1, *wt;
    cudaGetSymbolAddress((void**)&n1, g_n1);
    cudaGetSymbolAddress((void**)&n2x, g_n2x);
    cudaGetSymbolAddress((void**)&n2a, g_n2a);
    cudaGetSymbolAddress((void**)&qv, g_qv);
    cudaGetSymbolAddress((void**)&kb, g_k);
    cudaGetSymbolAddress((void**)&attn, g_attn);
    cudaGetSymbolAddress((void**)&ctx, g_ctx);
    cudaGetSymbolAddress((void**)&qh, g_qh_h);
    cudaGetSymbolAddress((void**)&q2, g_q2_h);
    cudaGetSymbolAddress((void**)&kh, g_kh_h);
    cudaGetSymbolAddress((void**)&k2, g_k2_h);
    cudaGetSymbolAddress((void**)&vrT, g_vrT);
    cudaGetSymbolAddress((void**)&tmp, g_tmp);
    cudaGetSymbolAddress((void**)&rectH, g_rectH);
    cudaGetSymbolAddress((void**)&xx, g_xx);
    cudaGetSymbolAddress((void**)&hdn, g_hdn);
    cudaGetSymbolAddress((void**)&h1, g_h1);
    cudaGetSymbolAddress((void**)&wt, g_wt);

    // 0) weight transpose-convert (one launch); zero K-pads of tmp/vrT
    transpose_all<<<1728, dim3(32, 8)>>>(Wqk, Wqk2, Wv, Wr_proj, W1, W2, wt);
    zero_pads<<<BH_*N_ + BH_*HD_, 32>>>(tmp, vrT);

    // 1) LayerNorms
    ln_kernel<<<26, 128>>>(x, n1, g1, b1, 26, 26, 0, (long)T_*C_, 0);
    ln_kernel<<<B_*N_, 128>>>(x + C_, n2x, g2, b2, B_*N_, N_, (long)T_*C_, C_, 1);
    ln_kernel<<<NC_*N_, 128>>>(x + (long)16*T_*C_ + C_, n2a, g2, b2, NC_*N_, N_, (long)T_*C_, C_, 1);

    // 2) cls path (fp32)
    rowgemm<<<dim3(NC_, 12), 256>>>(n1 + 16*C_, Wqv, nullptr, qv, 2*C_, 2*C_);
    rowgemm<<<dim3(B_, 6), 256>>>(n1, Wk, nullptr, kb, C_, C_);
    attn_cls_kernel<<<B_, 384>>>(qv, kb, attn, ctx);
    rowgemm<<<dim3(B_, 6), 256>>>(ctx, Wq_proj, bq_proj, xx, C_, (long)T_*C_);

    // 3) head projections (fp16 GEMMs, pipelined)
    dim3 gx(6, 25), ga(6, 16);
    gemm_h<<<gx, 256>>>(n2x, wt + OW_QK,  nullptr, nullptr, nullptr, qh,
                        B_*N_, C_, C_, C_, C_, 0, 1, 0, 0);
    gemm_h<<<gx, 256>>>(n2x, wt + OW_QK2, nullptr, nullptr, nullptr, q2,
                        B_*N_, C_, C_, C_, C_, 0, 1, 0, 0);
    gemm_h<<<gx, 256>>>(n2x, wt + OW_V,   nullptr, nullptr, nullptr, vrT,
                        B_*N_, C_, C_, C_, C_, 0, 4, 0, 0);
    gemm_h<<<ga, 256>>>(n2a, wt + OW_QK,  nullptr, nullptr, nullptr, kh,
                        NC_*N_, C_, C_, C_, C_, 0, 1, 0, 0);
    gemm_h<<<ga, 256>>>(n2a, wt + OW_QK2, nullptr, nullptr, nullptr, k2,
                        NC_*N_, C_, C_, C_, C_, 0, 1, 0, 0);

    // 4) fused rectified attention core -> tmp (fp16, K-padded)
    dim3 gf(2, 2, BH_);
    fused_attn3<<<gf, 256>>>(qh, kh, q2, k2, attn, tmp);

    // 5) rect = tmp @ vr (all-fp16, batched over bh) -> rectH flat [bh][n][d]
    gemm_h<<<dim3(1, 2, BH_), 256>>>(tmp, vrT, nullptr, nullptr, nullptr, rectH,
                                     N_, HD_, KP_, KP_, KP_, 0, 5,
                                     (long)N_*KP_, (long)HD_*KP_);

    // 6) rect projection + residual -> xx rows 1..196 (fp32)
    gemm_h<<<gx, 256>>>(rectH, wt + OW_R, br_proj, x, xx, nullptr,
                        B_*N_, C_, C_, C_, C_, 0, 2, 0, 0);

    // 7) MLP
    ln_kernel<<<B_*T_, 128>>>(xx, hdn, g3, b3, B_*T_, B_*T_, 0, C_, 1);
    gemm_h<<<dim3(24, 25), 256>>>(hdn, wt + OW_1, bm1, nullptr, nullptr, h1,
                                  B_*T_, 4*C_, C_, C_, C_, 1, 0, 0, 0);
    gemm_h<<<dim3(6, 25), 256>>>(h1, wt + OW_2, bm2, xx, outp, nullptr,
                                 B_*T_, C_, 4*C_, 4*C_, 4*C_, 0, 0, 0, 0);

    // 8) anchors pass-through
    int n4 = NC_*T_*C_/4;
    copy_kernel<<<(n4 + 255)/256, 256>>>(x + (long)16*T_*C_, outp + (long)16*T_*C_, n4);
}

// round 12
// speedup vs baseline: 2.4515x; 1.0502x over previous
#include <cuda_runtime.h>
#include <cuda_fp16.h>
#include <cstdint>

#define B_  16
#define NC_ 10
#define H_  6
#define C_  384
#define HD_ 64
#define T_  197
#define N_  196
#define BH_ (B_*H_)
#define CH_ (NC_*H_)
#define SCALE_ 0.125f
#define KP_ 224

#define OW_QK  0
#define OW_QK2 147456
#define OW_V   294912
#define OW_R   442368
#define OW_1   589824
#define OW_2   1179648
#define WT_TOT 1769472

__device__ float g_n1 [26*C_];
__device__ __align__(16) __half g_n2[26*N_*C_];    // image-token LN: batches 0..25
__device__ float g_qv [NC_*2*C_];
__device__ float g_k  [B_*C_];
__device__ float g_attn[B_*CH_];
__device__ float g_ctx[B_*C_];
__device__ __align__(16) __half g_qh_h[BH_*N_*HD_];
__device__ __align__(16) __half g_q2_h[BH_*N_*HD_];
__device__ __align__(16) __half g_kh_h[CH_*N_*HD_];
__device__ __align__(16) __half g_k2_h[CH_*N_*HD_];
__device__ __align__(16) __half g_vrT[BH_*HD_*KP_];
__device__ __align__(16) __half g_tmp[BH_*N_*KP_];
__device__ __align__(16) __half g_rectH[B_*N_*C_];
__device__ float g_xx [B_*T_*C_];
__device__ __align__(16) __half g_hdn[B_*T_*C_];
__device__ __align__(16) __half g_h1 [B_*T_*4*C_];
__device__ __align__(16) __half g_wt [WT_TOT];

#define U32(x) __float_as_uint(x)

__device__ __forceinline__ void mma16h(float* c, uint32_t a0, uint32_t a1, uint32_t a2, uint32_t a3,
                                       uint32_t b0, uint32_t b1)
{
    asm volatile("mma.sync.aligned.m16n8k16.row.col.f32.f16.f16.f32 "
                 "{%0,%1,%2,%3},{%4,%5,%6,%7},{%8,%9},{%0,%1,%2,%3};\n"
                 : "+f"(c[0]), "+f"(c[1]), "+f"(c[2]), "+f"(c[3])
                 : "r"(a0), "r"(a1), "r"(a2), "r"(a3), "r"(b0), "r"(b1));
}

__device__ __forceinline__ uint32_t pack_hf2(float lo, float hi) {
    uint32_t d;
    asm("cvt.rn.f16x2.f32 %0, %1, %2;" : "=r"(d) : "f"(hi), "f"(lo));
    return d;
}

__device__ __forceinline__ void cp16(uint32_t dst, const void* src, bool p) {
    int sz = p ? 16 : 0;
    asm volatile("cp.async.cg.shared.global [%0], [%1], 16, %2;" :: "r"(dst), "l"(src), "r"(sz));
}

__device__ __forceinline__ float gelu_f(float x) {
    return 0.5f * x * (1.f + erff(x * 0.7071067811865475f));
}

// ---------------- merged weight transpose-convert ----------------
__global__ void transpose_all(const float* __restrict__ Wqk, const float* __restrict__ Wqk2,
                              const float* __restrict__ Wv,  const float* __restrict__ Wr,
                              const float* __restrict__ W1,  const float* __restrict__ W2,
                              __half* __restrict__ wt)
{
    __shared__ float tile[32][33];
    int bid = blockIdx.x;
    const float* src; __half* dst; int K, N, tn;
    if      (bid < 144)  { src = Wqk;  dst = wt + OW_QK;  K = C_;   N = C_;   tn = bid; }
    else if (bid < 288)  { src = Wqk2; dst = wt + OW_QK2; K = C_;   N = C_;   tn = bid - 144; }
    else if (bid < 432)  { src = Wv;   dst = wt + OW_V;   K = C_;   N = C_;   tn = bid - 288; }
    else if (bid < 576)  { src = Wr;   dst = wt + OW_R;   K = C_;   N = C_;   tn = bid - 432; }
    else if (bid < 1152) { src = W1;   dst = wt + OW_1;   K = C_;   N = 4*C_; tn = bid - 576; }
    else                 { src = W2;   dst = wt + OW_2;   K = 4*C_; N = C_;   tn = bid - 1152; }
    int ntx = N >> 5;
    int nb = (tn % ntx) * 32, kb = (tn / ntx) * 32;
    int tx = threadIdx.x, ty = threadIdx.y;
#pragma unroll
    for (int i = 0; i < 32; i += 8)
        tile[ty + i][tx] = src[(size_t)(kb + ty + i) * N + nb + tx];
    __syncthreads();
#pragma unroll
    for (int i = 0; i < 32; i += 8)
        dst[(size_t)(nb + ty + i) * K + kb + tx] = __float2half(tile[tx][ty + i]);
}

__global__ void zero_pads(__half* __restrict__ tmp, __half* __restrict__ vrT)
{
    int row = blockIdx.x;
    int t = threadIdx.x;
    if (t >= KP_ - N_) return;
    if (row < BH_*N_) tmp[(size_t)row*KP_ + N_ + t] = __float2half(0.f);
    else {
        int r2 = row - BH_*N_;
        vrT[(size_t)r2*KP_ + N_ + t] = __float2half(0.f);
    }
}

// ---------------- LayerNorm (fp32 or fp16 output) ----------------
__global__ void ln_kernel(const float* __restrict__ in, void* __restrict__ outv,
                          const float* __restrict__ g, const float* __restrict__ bt,
                          int rows, int inner, long outer_stride, long inner_stride, int h16)
{
    int row = blockIdx.x;
    if (row >= rows) return;
    const float* src = in + (long)(row / inner) * outer_stride + (long)(row % inner) * inner_stride;
    int t = threadIdx.x;
    float v[3]; float s = 0.f;
#pragma unroll
    for (int i = 0; i < 3; i++) { v[i] = src[t + i*128]; s += v[i]; }
    __shared__ float red[4];
#pragma unroll
    for (int o = 16; o > 0; o >>= 1) s += __shfl_xor_sync(0xffffffffu, s, o);
    if ((t & 31) == 0) red[t >> 5] = s;
    __syncthreads();
    float mean = (red[0] + red[1] + red[2] + red[3]) * (1.f/384.f);
    float q = 0.f;
#pragma unroll
    for (int i = 0; i < 3; i++) { float d = v[i] - mean; q += d*d; }
#pragma unroll
    for (int o = 16; o > 0; o >>= 1) q += __shfl_xor_sync(0xffffffffu, q, o);
    __syncthreads();
    if ((t & 31) == 0) red[t >> 5] = q;
    __syncthreads();
    float var = (red[0] + red[1] + red[2] + red[3]) * (1.f/384.f);
    float rs = rsqrtf(var + 1e-5f);
#pragma unroll
    for (int i = 0; i < 3; i++) {
        int c = t + i*128;
        float o = (v[i] - mean) * rs * g[c] + bt[c];
        if (h16) ((__half*)outv)[(long)row*C_ + c] = __float2half(o);
        else     ((float*)outv)[(long)row*C_ + c] = o;
    }
}

// ---------------- merged cls qv/k row GEMM ----------------
__global__ __launch_bounds__(256)
void rowgemm_cls(const float* __restrict__ n1, const float* __restrict__ Wqv,
                 const float* __restrict__ Wk, float* __restrict__ qv, float* __restrict__ kb)
{
    __shared__ float a_s[384];
    __shared__ float part[256];
    int bx = blockIdx.x, by = blockIdx.y;
    const float* A; const float* W; float* out; int N;
    if (bx < NC_) { A = n1 + (16+bx)*C_; W = Wqv; out = qv + bx*2*C_; N = 2*C_; }
    else {
        if (by >= 6) return;
        A = n1 + (bx-NC_)*C_; W = Wk; out = kb + (bx-NC_)*C_; N = C_;
    }
    int cb = by * 64;
    int t = threadIdx.x;
    for (int i = t; i < 384; i += 256) a_s[i] = A[i];
    __syncthreads();
    int col = t & 63, sp = t >> 6;
    int base = sp * 96;
    float s0 = 0.f, s1 = 0.f;
    const float* Wp = W + (size_t)base*N + cb + col;
#pragma unroll 8
    for (int k = 0; k < 96; k += 2) {
        s0 += a_s[base+k]   * Wp[(size_t)(k)*N];
        s1 += a_s[base+k+1] * Wp[(size_t)(k+1)*N];
    }
    part[t] = s0 + s1;
    __syncthreads();
    if (t < 64) out[cb + t] = part[t] + part[64+t] + part[128+t] + part[192+t];
}

// ---------------- cls proj rowgemm (ctx @ Wq_proj) ----------------
__global__ __launch_bounds__(256)
void rowgemm(const float* __restrict__ A, const float* __restrict__ W,
             const float* __restrict__ bias, float* __restrict__ out,
             int N, long out_stride)
{
    __shared__ float a_s[384];
    __shared__ float part[256];
    int row = blockIdx.x, cb = blockIdx.y * 64;
    int t = threadIdx.x;
    for (int i = t; i < 384; i += 256) a_s[i] = A[(size_t)row*384 + i];
    __syncthreads();
    int col = t & 63, sp = t >> 6;
    int base = sp * 96;
    float s0 = 0.f, s1 = 0.f;
    const float* Wp = W + (size_t)base*N + cb + col;
#pragma unroll 8
    for (int k = 0; k < 96; k += 2) {
        s0 += a_s[base+k]   * Wp[(size_t)(k)*N];
        s1 += a_s[base+k+1] * Wp[(size_t)(k+1)*N];
    }
    part[t] = s0 + s1;
    __syncthreads();
    if (t < 64) {
        float v = part[t] + part[64+t] + part[128+t] + part[192+t];
        if (bias) v += bias[cb + t];
        out[(size_t)row*out_stride + cb + t] = v;
    }
}

// ---------------- cls attention ----------------
__global__ void attn_cls_kernel(const float* __restrict__ qv, const float* __restrict__ k,
                                float* __restrict__ attn, float* __restrict__ ctx)
{
    int b = blockIdx.x, t = threadIdx.x;
    __shared__ float sl[CH_];
    if (t < CH_) {
        int n = t / H_, h = t % H_;
        float s = 0.f;
        for (int d = 0; d < HD_; d++) s += qv[n*2*C_ + h*HD_ + d] * k[b*C_ + h*HD_ + d];
        sl[t] = s * SCALE_;
    }
    __syncthreads();
    if (t < H_) {
        float mx = -1e30f;
        for (int n = 0; n < NC_; n++) mx = fmaxf(mx, sl[n*H_ + t]);
        float sum = 0.f;
        for (int n = 0; n < NC_; n++) { float e = expf(sl[n*H_ + t] - mx); sl[n*H_ + t] = e; sum += e; }
        float inv = 1.f / sum;
        for (int n = 0; n < NC_; n++) { sl[n*H_ + t] *= inv; attn[b*CH_ + n*H_ + t] = sl[n*H_ + t]; }
    }
    __syncthreads();
    {
        int h = t >> 6, d = t & 63;
        float s = 0.f;
        for (int n = 0; n < NC_; n++) s += sl[n*H_ + h] * qv[n*2*C_ + C_ + h*HD_ + d];
        ctx[b*C_ + t] = s;
    }
}

// ---------------- all-fp16 GEMM, 2-stage cp.async pipeline, occ 2 ----------------
__global__ __launch_bounds__(256, 2)
void gemm_h(const __half* __restrict__ A, const __half* __restrict__ Bt,
            const float* __restrict__ bias, const float* __restrict__ res,
            float* __restrict__ outF, __half* __restrict__ outH,
            int M, int N, int K, int lda, int ldb, int act, int mode,
            long zA, long zB)
{
    __shared__ __align__(16) __half As[2][128*40];
    __shared__ __align__(16) __half Bs[2][64*40];
    A  += (size_t)blockIdx.z * zA;
    Bt += (size_t)blockIdx.z * zB;

    int tid = threadIdx.x;
    int lane = tid & 31, warp = tid >> 5;
    int gid = lane >> 2, tig = lane & 3;
    int wm = warp >> 1, wn = warp & 1;
    int m0 = blockIdx.y * 128, n0 = blockIdx.x * 64;

    int ar = tid >> 1, ac = (tid & 1) * 16;
    int br = tid >> 2, bc = (tid & 3) * 8;

    uint32_t aB[2], bB[2];
#pragma unroll
    for (int s = 0; s < 2; s++) {
        aB[s] = (uint32_t)__cvta_generic_to_shared(&As[s][0]);
        bB[s] = (uint32_t)__cvta_generic_to_shared(&Bs[s][0]);
    }

    bool okA = (m0 + ar < M);
    int nk = K >> 5;

#define GISSUE(it_, st_) do { \
    int kk = (it_) * 32; \
    const __half* sa = A + (size_t)(m0 + ar) * lda + kk + ac; \
    cp16(aB[st_] + (ar*40 + ac)*2,      okA ? sa : (const __half*)A,       okA); \
    cp16(aB[st_] + (ar*40 + ac)*2 + 16, okA ? (sa + 8) : (const __half*)A, okA); \
    cp16(bB[st_] + (br*40 + bc)*2, Bt + (size_t)(n0 + br) * ldb + kk + bc, true); \
    asm volatile("cp.async.commit_group;" ::: "memory"); \
} while (0)

    float acc[2][4][4];
#pragma unroll
    for (int t = 0; t < 2; t++)
#pragma unroll
        for (int u = 0; u < 4; u++)
#pragma unroll
            for (int e = 0; e < 4; e++) acc[t][u][e] = 0.f;

    GISSUE(0, 0);

    for (int it = 0; it < nk; it++) {
        asm volatile("cp.async.wait_group 0;" ::: "memory");
        __syncthreads();
        int st = it & 1;
        if (it + 1 < nk) GISSUE(it + 1, st ^ 1);
        const __half* Af = As[st];
        const __half* Bf = Bs[st];
#pragma unroll
        for (int ks = 0; ks < 2; ks++) {
            int ko = ks * 16;
            uint32_t a[2][4];
#pragma unroll
            for (int t = 0; t < 2; t++) {
                int mb = wm*32 + t*16;
                a[t][0] = *(const uint32_t*)(Af + (mb+gid)*40   + ko + 2*tig);
                a[t][1] = *(const uint32_t*)(Af + (mb+gid+8)*40 + ko + 2*tig);
                a[t][2] = *(const uint32_t*)(Af + (mb+gid)*40   + ko + 2*tig + 8);
                a[t][3] = *(const uint32_t*)(Af + (mb+gid+8)*40 + ko + 2*tig + 8);
            }
#pragma unroll
            for (int u = 0; u < 4; u++) {
                int cb = wn*32 + u*8;
                uint32_t b0 = *(const uint32_t*)(Bf + (cb+gid)*40 + ko + 2*tig);
                uint32_t b1 = *(const uint32_t*)(Bf + (cb+gid)*40 + ko + 2*tig + 8);
                mma16h(acc[0][u], a[0][0],a[0][1],a[0][2],a[0][3], b0,b1);
                mma16h(acc[1][u], a[1][0],a[1][1],a[1][2],a[1][3], b0,b1);
            }
        }
    }
#undef GISSUE

    int bz = blockIdx.z;
#pragma unroll
    for (int t = 0; t < 2; t++) {
#pragma unroll
        for (int u = 0; u < 4; u++) {
            int rb = m0 + wm*32 + t*16 + gid;
            int cb = n0 + wn*32 + u*8 + 2*tig;
#pragma unroll
            for (int e = 0; e < 4; e++) {
                int r = rb + (e >> 1) * 8;
                int c = cb + (e & 1);
                if (r >= M) continue;
                float v = acc[t][u][e];
                if (bias) v += bias[c];
                if (act) v = gelu_f(v);
                size_t idx;
                if (mode == 0) idx = (size_t)r * N + c;
                else if (mode == 1) {
                    int bq = r / N_, n = r % N_;
                    idx = ((size_t)(bq*H_ + (c >> 6)) * N_ + n) * HD_ + (c & 63);
                } else if (mode == 2) {
                    int bq = r / N_, n = r % N_;
                    idx = ((size_t)bq*T_ + 1 + n) * C_ + c;
                } else if (mode == 4) {
                    int bq = r / N_, n = r % N_;
                    idx = ((size_t)(bq*H_ + (c >> 6)) * HD_ + (c & 63)) * KP_ + n;
                } else { // 5: rectH flat [bh][n][d]
                    idx = ((size_t)bz * N_ + r) * HD_ + c;
                }
                if (outH) outH[idx] = __float2half(v);
                else {
                    if (res) v += res[idx];
                    outF[idx] = v;
                }
            }
        }
    }
}

// ---------------- fused rectified attention core (all-fp16, occ 2) ----------------
__global__ __launch_bounds__(256, 2)
void fused_attn3(const __half* __restrict__ qh, const __half* __restrict__ kh,
                 const __half* __restrict__ q2, const __half* __restrict__ k2,
                 const float* __restrict__ w2all, __half* __restrict__ tmp_out)
{
    __shared__ __align__(16) unsigned char smx[19712];
    __half* const stage = (__half*)smx;
    __half* const kbuf0 = (__half*)smx;
    __half* const kbuf1 = kbuf0 + 16*72;
    __half* const vbuf0 = kbuf1 + 16*72;
    __half* const vbuf1 = vbuf0 + 16*72;
    uint32_t* const L2_s  = (uint32_t*)(smx + 9216);
    uint32_t* const Rt2_s = (uint32_t*)(smx + 13568);

    int tid = threadIdx.x;
    int lane = tid & 31, warp = tid >> 5;
    int gid = lane >> 2, tig = lane & 3;
    int wm = warp >> 1, wn = warp & 1;

    int bh = blockIdx.z;
    int b = bh / H_, h = bh % H_;
    int n0 = blockIdx.y * 68;
    int p0 = blockIdx.x * 68;

    const __half* qh_b = qh + (size_t)bh * N_ * HD_;
    const __half* q2_b = q2 + (size_t)bh * N_ * HD_;

    uint32_t aq[4][4];
    for (int i = tid; i < 1024; i += 256) {
        int r = i >> 3, c8 = (i & 7) * 8;
        *(float4*)(stage + r*72 + c8) = *(const float4*)(qh_b + (size_t)(n0+r)*HD_ + c8);
    }
    __syncthreads();
    {
        int rb = warp * 16;
#pragma unroll
        for (int j = 0; j < 4; j++) {
            aq[j][0] = *(const uint32_t*)(stage + (rb+gid)*72   + 16*j + 2*tig);
            aq[j][1] = *(const uint32_t*)(stage + (rb+gid+8)*72 + 16*j + 2*tig);
            aq[j][2] = *(const uint32_t*)(stage + (rb+gid)*72   + 16*j + 2*tig + 8);
            aq[j][3] = *(const uint32_t*)(stage + (rb+gid+8)*72 + 16*j + 2*tig + 8);
        }
    }
    __syncthreads();
    uint32_t aq2[4][4];
    for (int i = tid; i < 1024; i += 256) {
        int r = i >> 3, c8 = (i & 7) * 8;
        *(float4*)(stage + r*72 + c8) = *(const float4*)(q2_b + (size_t)(p0+r)*HD_ + c8);
    }
    __syncthreads();
    {
        int pb = warp * 16;
#pragma unroll
        for (int j = 0; j < 4; j++) {
            aq2[j][0] = *(const uint32_t*)(stage + (pb+gid)*72   + 16*j + 2*tig);
            aq2[j][1] = *(const uint32_t*)(stage + (pb+gid+8)*72 + 16*j + 2*tig);
            aq2[j][2] = *(const uint32_t*)(stage + (pb+gid)*72   + 16*j + 2*tig + 8);
            aq2[j][3] = *(const uint32_t*)(stage + (pb+gid+8)*72 + 16*j + 2*tig + 8);
        }
    }
    __syncthreads();

    float acc[2][8][4];
#pragma unroll
    for (int t = 0; t < 2; t++)
#pragma unroll
        for (int u = 0; u < 8; u++)
#pragma unroll
            for (int e = 0; e < 4; e++) acc[t][u][e] = 0.f;

    uint32_t kd0 = (uint32_t)__cvta_generic_to_shared(kbuf0);
    uint32_t kd1 = (uint32_t)__cvta_generic_to_shared(kbuf1);
    uint32_t vd0 = (uint32_t)__cvta_generic_to_shared(vbuf0);
    uint32_t vd1 = (uint32_t)__cvta_generic_to_shared(vbuf1);

    int op  = tid >> 7;
    int pr  = (tid & 127) >> 3;
    int pc8 = (tid & 7) * 8;

    {
        const __half* src = (op ? k2 : kh) + (size_t)h * N_ * HD_ + (size_t)pr*HD_ + pc8;
        uint32_t d = (op ? vd0 : kd0) + (pr*72 + pc8)*2;
        cp16(d, src, true);
    }
    asm volatile("cp.async.commit_group;" ::: "memory");

    int buf = 0;
    for (int c = 0; c < NC_; c++) {
        float w2c = w2all[b*CH_ + h*NC_ + c];
        for (int mc = 0; mc < 13; mc++) {
            {
                int nc2 = c, nm = mc + 1;
                if (nm == 13) { nm = 0; nc2 = c + 1; }
                if (nc2 < NC_) {
                    int m = nm*16 + pr;
                    bool ok = m < N_;
                    const __half* basep = (op ? k2 : kh) + (size_t)(nc2*H_ + h) * N_ * HD_;
                    const __half* src = basep + (ok ? ((size_t)m*HD_ + pc8) : 0);
                    uint32_t d = (op ? (buf ? vd0 : vd1) : (buf ? kd0 : kd1)) + (pr*72 + pc8)*2;
                    cp16(d, src, ok);
                }
            }
            asm volatile("cp.async.commit_group;" ::: "memory");
            asm volatile("cp.async.wait_group 1;" ::: "memory");
            __syncthreads();

            const __half* KT  = buf ? kbuf1 : kbuf0;
            const __half* K2T = buf ? vbuf1 : vbuf0;

            float lacc[2][4];
#pragma unroll
            for (int t = 0; t < 2; t++)
#pragma unroll
                for (int e = 0; e < 4; e++) lacc[t][e] = 0.f;
#pragma unroll
            for (int j = 0; j < 4; j++) {
                uint32_t b0lo = *(const uint32_t*)(KT + gid*72     + 16*j + 2*tig);
                uint32_t b1lo = *(const uint32_t*)(KT + gid*72     + 16*j + 2*tig + 8);
                uint32_t b0hi = *(const uint32_t*)(KT + (gid+8)*72 + 16*j + 2*tig);
                uint32_t b1hi = *(const uint32_t*)(KT + (gid+8)*72 + 16*j + 2*tig + 8);
                mma16h(lacc[0], aq[j][0],aq[j][1],aq[j][2],aq[j][3], b0lo,b1lo);
                mma16h(lacc[1], aq[j][0],aq[j][1],aq[j][2],aq[j][3], b0hi,b1hi);
            }
            float racc[2][4];
#pragma unroll
            for (int t = 0; t < 2; t++)
#pragma unroll
                for (int e = 0; e < 4; e++) racc[t][e] = 0.f;
#pragma unroll
            for (int j = 0; j < 4; j++) {
                uint32_t b0lo = *(const uint32_t*)(K2T + gid*72     + 16*j + 2*tig);
                uint32_t b1lo = *(const uint32_t*)(K2T + gid*72     + 16*j + 2*tig + 8);
                uint32_t b0hi = *(const uint32_t*)(K2T + (gid+8)*72 + 16*j + 2*tig);
                uint32_t b1hi = *(const uint32_t*)(K2T + (gid+8)*72 + 16*j + 2*tig + 8);
                mma16h(racc[0], aq2[j][0],aq2[j][1],aq2[j][2],aq2[j][3], b0lo,b1lo);
                mma16h(racc[1], aq2[j][0],aq2[j][1],aq2[j][2],aq2[j][3], b0hi,b1hi);
            }
            {
                int nr = warp*16 + gid;
                int pb = warp*16;
#pragma unroll
                for (int t = 0; t < 2; t++) {
                    float l0 = w2c * fmaxf(0.f, -SCALE_*lacc[t][0]);
                    float l1 = w2c * fmaxf(0.f, -SCALE_*lacc[t][1]);
                    float l2 = w2c * fmaxf(0.f, -SCALE_*lacc[t][2]);
                    float l3 = w2c * fmaxf(0.f, -SCALE_*lacc[t][3]);
                    L2_s[(4*t+tig)*136 + nr]     = pack_hf2(l0, l1);
                    L2_s[(4*t+tig)*136 + nr + 8] = pack_hf2(l2, l3);
                    float r0 = fmaxf(0.f, SCALE_*racc[t][0]);
                    float r1 = fmaxf(0.f, SCALE_*racc[t][1]);
                    float r2 = fmaxf(0.f, SCALE_*racc[t][2]);
                    float r3 = fmaxf(0.f, SCALE_*racc[t][3]);
                    Rt2_s[(pb+gid)*12 + 4*t+tig]   = pack_hf2(r0, r1);
                    Rt2_s[(pb+gid+8)*12 + 4*t+tig] = pack_hf2(r2, r3);
                }
            }
            __syncthreads();
            {
                uint32_t a[2][4];
#pragma unroll
                for (int t = 0; t < 2; t++) {
                    int mb = wm*32 + t*16;
                    a[t][0] = L2_s[tig*136 + mb+gid];
                    a[t][1] = L2_s[tig*136 + mb+gid+8];
                    a[t][2] = L2_s[(tig+4)*136 + mb+gid];
                    a[t][3] = L2_s[(tig+4)*136 + mb+gid+8];
                }
#pragma unroll
                for (int u = 0; u < 8; u++) {
                    int cb = wn*64 + u*8;
                    uint32_t b0 = Rt2_s[(cb+gid)*12 + tig];
                    uint32_t b1 = Rt2_s[(cb+gid)*12 + tig+4];
                    mma16h(acc[0][u], a[0][0],a[0][1],a[0][2],a[0][3], b0,b1);
                    mma16h(acc[1][u], a[1][0],a[1][1],a[1][2],a[1][3], b0,b1);
                }
            }
            buf ^= 1;
        }
    }

    __half* o = tmp_out + (size_t)bh * N_ * KP_;
#pragma unroll
    for (int t = 0; t < 2; t++) {
#pragma unroll
        for (int u = 0; u < 8; u++) {
            int n = n0 + wm*32 + t*16 + gid;
            int p = p0 + wn*64 + u*8 + 2*tig;
            *(uint32_t*)(o + (size_t)n*KP_ + p)     = pack_hf2(acc[t][u][0], acc[t][u][1]);
            *(uint32_t*)(o + (size_t)(n+8)*KP_ + p) = pack_hf2(acc[t][u][2], acc[t][u][3]);
        }
    }
}

__global__ void copy_kernel(const float* __restrict__ src, float* __restrict__ dst, int n4)
{
    int i = blockIdx.x * blockDim.x + threadIdx.x;
    if (i < n4) ((float4*)dst)[i] = ((const float4*)src)[i];
}

extern "C" void kernel_launch(void* const* d_in, const int* in_sizes, int n_in,
                              void* d_out, int out_size)
{
    const float* x       = (const float*)d_in[0];
    const float* Wqv     = (const float*)d_in[1];
    const float* Wk      = (const float*)d_in[2];
    const float* Wq_proj = (const float*)d_in[3];
    const float* bq_proj = (const float*)d_in[4];
    const float* Wqk     = (const float*)d_in[5];
    const float* Wqk2    = (const float*)d_in[6];
    const float* Wv      = (const float*)d_in[7];
    const float* Wr_proj = (const float*)d_in[8];
    const float* br_proj = (const float*)d_in[9];
    const float* g1      = (const float*)d_in[10];
    const float* b1      = (const float*)d_in[11];
    const float* g2      = (const float*)d_in[12];
    const float* b2      = (const float*)d_in[13];
    const float* g3      = (const float*)d_in[14];
    const float* b3      = (const float*)d_in[15];
    const float* W1      = (const float*)d_in[16];
    const float* bm1     = (const float*)d_in[17];
    const float* W2      = (const float*)d_in[18];
    const float* bm2     = (const float*)d_in[19];
    float* outp = (float*)d_out;

    float *n1, *qv, *kb, *attn, *ctx, *xx;
    __half *n2, *qh, *q2, *kh, *k2, *vrT, *tmp, *rectH, *hdn, *h1, *wt;
    cudaGetSymbolAddress((void**)&n1, g_n1);
    cudaGetSymbolAddress((void**)&n2, g_n2);
    cudaGetSymbolAddress((void**)&qv, g_qv);
    cudaGetSymbolAddress((void**)&kb, g_k);
    cudaGetSymbolAddress((void**)&attn, g_attn);
    cudaGetSymbolAddress((void**)&ctx, g_ctx);
    cudaGetSymbolAddress((void**)&qh, g_qh_h);
    cudaGetSymbolAddress((void**)&q2, g_q2_h);
    cudaGetSymbolAddress((void**)&kh, g_kh_h);
    cudaGetSymbolAddress((void**)&k2, g_k2_h);
    cudaGetSymbolAddress((void**)&vrT, g_vrT);
    cudaGetSymbolAddress((void**)&tmp, g_tmp);
    cudaGetSymbolAddress((void**)&rectH, g_rectH);
    cudaGetSymbolAddress((void**)&xx, g_xx);
    cudaGetSymbolAddress((void**)&hdn, g_hdn);
    cudaGetSymbolAddress((void**)&h1, g_h1);
    cudaGetSymbolAddress((void**)&wt, g_wt);

    __half* n2x = n2;                       // batches 0..15
    __half* n2a = n2 + (size_t)B_*N_*C_;    // batches 16..25

    // 0) weight transpose-convert; zero K-pads
    transpose_all<<<1728, dim3(32, 8)>>>(Wqk, Wqk2, Wv, Wr_proj, W1, W2, wt);
    zero_pads<<<BH_*N_ + BH_*HD_, 32>>>(tmp, vrT);

    // 1) LayerNorms (cls fp32; ALL image tokens batches 0..25 in one launch)
    ln_kernel<<<26, 128>>>(x, n1, g1, b1, 26, 26, 0, (long)T_*C_, 0);
    ln_kernel<<<26*N_, 128>>>(x + C_, n2, g2, b2, 26*N_, N_, (long)T_*C_, C_, 1);

    // 2) cls path (merged qv/k launch)
    rowgemm_cls<<<dim3(26, 12), 256>>>(n1, Wqv, Wk, qv, kb);
    attn_cls_kernel<<<B_, 384>>>(qv, kb, attn, ctx);
    rowgemm<<<dim3(B_, 6), 256>>>(ctx, Wq_proj, bq_proj, xx, C_, (long)T_*C_);

    // 3) head projections
    dim3 gx(6, 25), ga(6, 16);
    gemm_h<<<gx, 256>>>(n2x, wt + OW_QK,  nullptr, nullptr, nullptr, qh,
                        B_*N_, C_, C_, C_, C_, 0, 1, 0, 0);
    gemm_h<<<gx, 256>>>(n2x, wt + OW_QK2, nullptr, nullptr, nullptr, q2,
                        B_*N_, C_, C_, C_, C_, 0, 1, 0, 0);
    gemm_h<<<gx, 256>>>(n2x, wt + OW_V,   nullptr, nullptr, nullptr, vrT,
                        B_*N_, C_, C_, C_, C_, 0, 4, 0, 0);
    gemm_h<<<ga, 256>>>(n2a, wt + OW_QK,  nullptr, nullptr, nullptr, kh,
                        NC_*N_, C_, C_, C_, C_, 0, 1, 0, 0);
    gemm_h<<<ga, 256>>>(n2a, wt + OW_QK2, nullptr, nullptr, nullptr, k2,
                        NC_*N_, C_, C_, C_, C_, 0, 1, 0, 0);

    // 4) fused rectified attention core -> tmp
    dim3 gf(2, 2, BH_);
    fused_attn3<<<gf, 256>>>(qh, kh, q2, k2, attn, tmp);

    // 5) rect = tmp @ vr -> rectH flat [bh][n][d]
    gemm_h<<<dim3(1, 2, BH_), 256>>>(tmp, vrT, nullptr, nullptr, nullptr, rectH,
                                     N_, HD_, KP_, KP_, KP_, 0, 5,
                                     (long)N_*KP_, (long)HD_*KP_);

    // 6) rect projection + residual -> xx rows 1..196
    gemm_h<<<gx, 256>>>(rectH, wt + OW_R, br_proj, x, xx, nullptr,
                        B_*N_, C_, C_, C_, C_, 0, 2, 0, 0);

    // 7) MLP
    ln_kernel<<<B_*T_, 128>>>(xx, hdn, g3, b3, B_*T_, B_*T_, 0, C_, 1);
    gemm_h<<<dim3(24, 25), 256>>>(hdn, wt + OW_1, bm1, nullptr, nullptr, h1,
                                  B_*T_, 4*C_, C_, C_, C_, 1, 0, 0, 0);
    gemm_h<<<dim3(6, 25), 256>>>(h1, wt + OW_2, bm2, xx, outp, nullptr,
                                 B_*T_, C_, 4*C_, 4*C_, 4*C_, 0, 0, 0, 0);

    // 8) anchors pass-through
    int n4 = NC_*T_*C_/4;
    copy_kernel<<<(n4 + 255)/256, 256>>>(x + (long)16*T_*C_, outp + (long)16*T_*C_, n4);
}